// round 1
// baseline (speedup 1.0000x reference)
#include <cuda_runtime.h>
#include <math.h>
#include <stdint.h>

// Problem dims (fixed by the reference)
#define NB   8
#define SEQ  1024
#define TOK  (NB * SEQ)       // 8192
#define D    1152
#define FFD  4608
#define NH   16
#define HD   72               // head dim

// ---------------------------------------------------------------------------
// Scratch (device globals — no allocations allowed)
// ---------------------------------------------------------------------------
__device__ float g_xln[(size_t)TOK * D];            // LN output (reused for ln1, ln2)
__device__ float g_q[(size_t)TOK * D];
__device__ float g_k[(size_t)TOK * D];
__device__ float g_v[(size_t)TOK * D];
__device__ float g_scores[(size_t)NB * NH * SEQ * SEQ];  // 512 MB
__device__ float g_attno[(size_t)TOK * D];
__device__ float g_h2[(size_t)TOK * D];
__device__ float g_ff[(size_t)TOK * FFD];

// ---------------------------------------------------------------------------
// LayerNorm: one block per row, 288 threads, one float4 per thread (288*4=1152)
// ---------------------------------------------------------------------------
__global__ void ln_kernel(const float* __restrict__ X, const float* __restrict__ gamma,
                          const float* __restrict__ beta, float* __restrict__ Y) {
    int row = blockIdx.x;
    int tid = threadIdx.x;
    float4 v = ((const float4*)(X + (size_t)row * D))[tid];
    float s  = v.x + v.y + v.z + v.w;
    float sq = v.x * v.x + v.y * v.y + v.z * v.z + v.w * v.w;
    #pragma unroll
    for (int o = 16; o > 0; o >>= 1) {
        s  += __shfl_down_sync(0xffffffffu, s,  o);
        sq += __shfl_down_sync(0xffffffffu, sq, o);
    }
    __shared__ float ss[9], ssq[9];
    int w = tid >> 5, l = tid & 31;
    if (l == 0) { ss[w] = s; ssq[w] = sq; }
    __syncthreads();
    float ts = 0.f, tsq = 0.f;
    #pragma unroll
    for (int i = 0; i < 9; i++) { ts += ss[i]; tsq += ssq[i]; }
    const float invD = 1.0f / (float)D;
    float mean = ts * invD;
    float var  = tsq * invD - mean * mean;
    float rinv = rsqrtf(var + 1e-5f);
    float4 g = ((const float4*)gamma)[tid];
    float4 b = ((const float4*)beta)[tid];
    float4 o;
    o.x = (v.x - mean) * rinv * g.x + b.x;
    o.y = (v.y - mean) * rinv * g.y + b.y;
    o.z = (v.z - mean) * rinv * g.z + b.z;
    o.w = (v.w - mean) * rinv * g.w + b.w;
    ((float4*)(Y + (size_t)row * D))[tid] = o;
}

// ---------------------------------------------------------------------------
// SGEMM: C[M,N] = A[M,K] @ W[K,N] + bias (+ GELU) (+ residual)
// 128x128 tile, BK=8, 256 threads, 8x8 microtile.
// Requires M%128==0, N%128==0, K%8==0 (all shapes here satisfy this).
// ---------------------------------------------------------------------------
__global__ __launch_bounds__(256, 2)
void sgemm_kernel(const float* __restrict__ A, const float* __restrict__ W,
                  const float* __restrict__ bias, const float* __restrict__ res,
                  float* __restrict__ C, int M, int N, int K, int gelu_act)
{
    __shared__ float As[8][128];
    __shared__ float Ws[8][132];   // padded
    int tid  = threadIdx.x;
    int brow = blockIdx.y * 128;
    int bcol = blockIdx.x * 128;
    int a_row = tid >> 1;
    int a_col = (tid & 1) << 2;
    int w_row = tid >> 5;
    int w_col = (tid & 31) << 2;
    int tx = (tid & 15) << 3;      // column base within tile
    int ty = (tid >> 4) << 3;      // row base within tile
    float acc[8][8];
    #pragma unroll
    for (int i = 0; i < 8; i++)
        #pragma unroll
        for (int j = 0; j < 8; j++) acc[i][j] = 0.f;

    const float* Ap = A + (size_t)(brow + a_row) * K + a_col;
    const float* Wp = W + (size_t)w_row * N + bcol + w_col;

    for (int k0 = 0; k0 < K; k0 += 8) {
        float4 av = *(const float4*)(Ap + k0);
        As[a_col + 0][a_row] = av.x;
        As[a_col + 1][a_row] = av.y;
        As[a_col + 2][a_row] = av.z;
        As[a_col + 3][a_row] = av.w;
        float4 wv = *(const float4*)(Wp + (size_t)k0 * N);
        *(float4*)&Ws[w_row][w_col] = wv;
        __syncthreads();
        #pragma unroll
        for (int kk = 0; kk < 8; kk++) {
            float af[8], bf[8];
            *(float4*)&af[0] = *(const float4*)&As[kk][ty];
            *(float4*)&af[4] = *(const float4*)&As[kk][ty + 4];
            *(float4*)&bf[0] = *(const float4*)&Ws[kk][tx];
            *(float4*)&bf[4] = *(const float4*)&Ws[kk][tx + 4];
            #pragma unroll
            for (int i = 0; i < 8; i++)
                #pragma unroll
                for (int j = 0; j < 8; j++)
                    acc[i][j] = fmaf(af[i], bf[j], acc[i][j]);
        }
        __syncthreads();
    }

    #pragma unroll
    for (int i = 0; i < 8; i++) {
        size_t row = (size_t)(brow + ty + i);
        #pragma unroll
        for (int j4 = 0; j4 < 8; j4 += 4) {
            int col = bcol + tx + j4;
            float4 o;
            o.x = acc[i][j4 + 0] + bias[col + 0];
            o.y = acc[i][j4 + 1] + bias[col + 1];
            o.z = acc[i][j4 + 2] + bias[col + 2];
            o.w = acc[i][j4 + 3] + bias[col + 3];
            if (gelu_act) {
                o.x = 0.5f * o.x * (1.0f + erff(o.x * 0.70710678118f));
                o.y = 0.5f * o.y * (1.0f + erff(o.y * 0.70710678118f));
                o.z = 0.5f * o.z * (1.0f + erff(o.z * 0.70710678118f));
                o.w = 0.5f * o.w * (1.0f + erff(o.w * 0.70710678118f));
            }
            if (res) {
                float4 r = *(const float4*)(res + row * N + col);
                o.x += r.x; o.y += r.y; o.z += r.z; o.w += r.w;
            }
            *(float4*)(C + row * N + col) = o;
        }
    }
}

// ---------------------------------------------------------------------------
// Scores: S[b,h,i,j] = scale * sum_d Q[b,i,h,d] * K[b,j,h,d]
// One block computes a 64x64 tile for one (b,h). 256 threads, 4x4 microtile.
// ---------------------------------------------------------------------------
__global__ void scores_kernel(const float* __restrict__ Q, const float* __restrict__ Km,
                              float* __restrict__ S) {
    int bh = blockIdx.z;
    int b = bh >> 4, h = bh & 15;
    int row0 = blockIdx.y * 64;
    int col0 = blockIdx.x * 64;
    const float* qbase = Q + (size_t)b * SEQ * D + h * HD;
    const float* kbase = Km + (size_t)b * SEQ * D + h * HD;
    __shared__ float Qs[64][76];
    __shared__ float Ks[64][76];
    int tid = threadIdx.x;   // 256
    for (int i = tid; i < 64 * 72; i += 256) {
        int r = i / 72, c = i % 72;
        Qs[r][c] = qbase[(size_t)(row0 + r) * D + c];
        Ks[r][c] = kbase[(size_t)(col0 + r) * D + c];
    }
    __syncthreads();
    int tx = tid & 15, ty = tid >> 4;
    float acc[4][4] = {};
    #pragma unroll 6
    for (int d = 0; d < 72; d += 4) {
        float qr[4][4], kr[4][4];
        #pragma unroll
        for (int i = 0; i < 4; i++) {
            float4 t = *(const float4*)&Qs[ty * 4 + i][d];
            qr[i][0] = t.x; qr[i][1] = t.y; qr[i][2] = t.z; qr[i][3] = t.w;
        }
        #pragma unroll
        for (int j = 0; j < 4; j++) {
            float4 t = *(const float4*)&Ks[tx * 4 + j][d];
            kr[j][0] = t.x; kr[j][1] = t.y; kr[j][2] = t.z; kr[j][3] = t.w;
        }
        #pragma unroll
        for (int t = 0; t < 4; t++)
            #pragma unroll
            for (int i = 0; i < 4; i++)
                #pragma unroll
                for (int j = 0; j < 4; j++)
                    acc[i][j] = fmaf(qr[i][t], kr[j][t], acc[i][j]);
    }
    const float scale = 0.117851130198f;   // 72^-0.5
    float* sbase = S + (size_t)bh * SEQ * SEQ;
    #pragma unroll
    for (int i = 0; i < 4; i++) {
        float4 o;
        o.x = acc[i][0] * scale; o.y = acc[i][1] * scale;
        o.z = acc[i][2] * scale; o.w = acc[i][3] * scale;
        *(float4*)(sbase + (size_t)(row0 + ty * 4 + i) * SEQ + col0 + tx * 4) = o;
    }
}

// ---------------------------------------------------------------------------
// Softmax over last dim (1024). One block per row, 256 threads, float4 each.
// ---------------------------------------------------------------------------
__global__ void softmax_kernel(float* __restrict__ S) {
    float* p = S + (size_t)blockIdx.x * SEQ;
    int tid = threadIdx.x;
    float4 v = ((float4*)p)[tid];
    float m = fmaxf(fmaxf(v.x, v.y), fmaxf(v.z, v.w));
    #pragma unroll
    for (int o = 16; o > 0; o >>= 1) m = fmaxf(m, __shfl_xor_sync(0xffffffffu, m, o));
    __shared__ float sm[8], ssum[8];
    int w = tid >> 5, l = tid & 31;
    if (l == 0) sm[w] = m;
    __syncthreads();
    float M = fmaxf(fmaxf(fmaxf(sm[0], sm[1]), fmaxf(sm[2], sm[3])),
                    fmaxf(fmaxf(sm[4], sm[5]), fmaxf(sm[6], sm[7])));
    v.x = __expf(v.x - M);
    v.y = __expf(v.y - M);
    v.z = __expf(v.z - M);
    v.w = __expf(v.w - M);
    float s = v.x + v.y + v.z + v.w;
    #pragma unroll
    for (int o = 16; o > 0; o >>= 1) s += __shfl_xor_sync(0xffffffffu, s, o);
    if (l == 0) ssum[w] = s;
    __syncthreads();
    float T = ((ssum[0] + ssum[1]) + (ssum[2] + ssum[3])) +
              ((ssum[4] + ssum[5]) + (ssum[6] + ssum[7]));
    float inv = 1.0f / T;
    v.x *= inv; v.y *= inv; v.z *= inv; v.w *= inv;
    ((float4*)p)[tid] = v;
}

// ---------------------------------------------------------------------------
// PV: O[b,i,h,:] = sum_j P[b,h,i,j] * V[b,j,h,:]
// One block: 64 rows x 72 cols for one (b,h). 288 threads (16x18), 4x4 microtile.
// ---------------------------------------------------------------------------
__global__ void av_kernel(const float* __restrict__ P, const float* __restrict__ V,
                          float* __restrict__ O) {
    int bh = blockIdx.y;
    int b = bh >> 4, h = bh & 15;
    int row0 = blockIdx.x * 64;
    const float* pbase = P + (size_t)bh * SEQ * SEQ;
    const float* vbase = V + (size_t)b * SEQ * D + h * HD;
    __shared__ float Ps[64][36];
    __shared__ float Vs[32][76];
    int tid = threadIdx.x;        // 288
    int tx = tid % 18;            // col group: cols tx*4 .. tx*4+3  (72 cols)
    int ty = tid / 18;            // 0..15 -> rows ty*4 .. ty*4+3
    float acc[4][4] = {};
    for (int k0 = 0; k0 < SEQ; k0 += 32) {
        for (int i = tid; i < 64 * 32; i += 288) {
            int r = i >> 5, c = i & 31;
            Ps[r][c] = pbase[(size_t)(row0 + r) * SEQ + k0 + c];
        }
        for (int i = tid; i < 32 * 72; i += 288) {
            int r = i / 72, c = i % 72;
            Vs[r][c] = vbase[(size_t)(k0 + r) * D + c];
        }
        __syncthreads();
        #pragma unroll 8
        for (int kk = 0; kk < 32; kk += 4) {
            float pr[4][4];
            #pragma unroll
            for (int i = 0; i < 4; i++) {
                float4 t = *(const float4*)&Ps[ty * 4 + i][kk];
                pr[i][0] = t.x; pr[i][1] = t.y; pr[i][2] = t.z; pr[i][3] = t.w;
            }
            #pragma unroll
            for (int t = 0; t < 4; t++) {
                float4 vv = *(const float4*)&Vs[kk + t][tx * 4];
                #pragma unroll
                for (int i = 0; i < 4; i++) {
                    acc[i][0] = fmaf(pr[i][t], vv.x, acc[i][0]);
                    acc[i][1] = fmaf(pr[i][t], vv.y, acc[i][1]);
                    acc[i][2] = fmaf(pr[i][t], vv.z, acc[i][2]);
                    acc[i][3] = fmaf(pr[i][t], vv.w, acc[i][3]);
                }
            }
        }
        __syncthreads();
    }
    #pragma unroll
    for (int i = 0; i < 4; i++) {
        size_t row = (size_t)b * SEQ + row0 + ty * 4 + i;
        float4 o;
        o.x = acc[i][0]; o.y = acc[i][1]; o.z = acc[i][2]; o.w = acc[i][3];
        *(float4*)(O + row * D + h * HD + tx * 4) = o;
    }
}

// ---------------------------------------------------------------------------
// Launch
// ---------------------------------------------------------------------------
extern "C" void kernel_launch(void* const* d_in, const int* in_sizes, int n_in,
                              void* d_out, int out_size) {
    const float* hs    = (const float*)d_in[0];
    const float* ln1_w = (const float*)d_in[1];
    const float* ln1_b = (const float*)d_in[2];
    const float* q_w   = (const float*)d_in[3];
    const float* q_b   = (const float*)d_in[4];
    const float* k_w   = (const float*)d_in[5];
    const float* k_b   = (const float*)d_in[6];
    const float* v_w   = (const float*)d_in[7];
    const float* v_b   = (const float*)d_in[8];
    const float* o_w   = (const float*)d_in[9];
    const float* o_b   = (const float*)d_in[10];
    const float* ln2_w = (const float*)d_in[11];
    const float* ln2_b = (const float*)d_in[12];
    const float* fc1_w = (const float*)d_in[13];
    const float* fc1_b = (const float*)d_in[14];
    const float* fc2_w = (const float*)d_in[15];
    const float* fc2_b = (const float*)d_in[16];
    float* out = (float*)d_out;

    float *xln, *q, *k, *v, *sc, *ao, *h2, *ff;
    cudaGetSymbolAddress((void**)&xln, g_xln);
    cudaGetSymbolAddress((void**)&q,   g_q);
    cudaGetSymbolAddress((void**)&k,   g_k);
    cudaGetSymbolAddress((void**)&v,   g_v);
    cudaGetSymbolAddress((void**)&sc,  g_scores);
    cudaGetSymbolAddress((void**)&ao,  g_attno);
    cudaGetSymbolAddress((void**)&h2,  g_h2);
    cudaGetSymbolAddress((void**)&ff,  g_ff);

    dim3 gD(D / 128, TOK / 128);      // (9, 64)
    dim3 gF(FFD / 128, TOK / 128);    // (36, 64)

    // 1. LN1
    ln_kernel<<<TOK, 288>>>(hs, ln1_w, ln1_b, xln);
    // 2. Q, K, V projections
    sgemm_kernel<<<gD, 256>>>(xln, q_w, q_b, nullptr, q, TOK, D, D, 0);
    sgemm_kernel<<<gD, 256>>>(xln, k_w, k_b, nullptr, k, TOK, D, D, 0);
    sgemm_kernel<<<gD, 256>>>(xln, v_w, v_b, nullptr, v, TOK, D, D, 0);
    // 3. scores = scale * Q K^T
    scores_kernel<<<dim3(SEQ / 64, SEQ / 64, NB * NH), 256>>>(q, k, sc);
    // 4. softmax
    softmax_kernel<<<NB * NH * SEQ, 256>>>(sc);
    // 5. attn @ V
    av_kernel<<<dim3(SEQ / 64, NB * NH), 288>>>(sc, v, ao);
    // 6. O projection + residual1
    sgemm_kernel<<<gD, 256>>>(ao, o_w, o_b, hs, h2, TOK, D, D, 0);
    // 7. LN2
    ln_kernel<<<TOK, 288>>>(h2, ln2_w, ln2_b, xln);
    // 8. FC1 + exact GELU
    sgemm_kernel<<<gF, 256>>>(xln, fc1_w, fc1_b, nullptr, ff, TOK, FFD, D, 1);
    // 9. FC2 + residual2 -> out
    sgemm_kernel<<<gD, 256>>>(ff, fc2_w, fc2_b, h2, out, TOK, D, FFD, 0);
}

// round 2
// speedup vs baseline: 1.9719x; 1.9719x over previous
#include <cuda_runtime.h>
#include <math.h>
#include <stdint.h>

// Problem dims (fixed by the reference)
#define NB   8
#define SEQ  1024
#define TOK  (NB * SEQ)       // 8192
#define D    1152
#define FFD  4608
#define NH   16
#define HD   72               // head dim

// ---------------------------------------------------------------------------
// Scratch (device globals — no allocations allowed)
// ---------------------------------------------------------------------------
__device__ float g_xln[(size_t)TOK * D];
__device__ float g_q[(size_t)TOK * D];
__device__ float g_k[(size_t)TOK * D];
__device__ float g_v[(size_t)TOK * D];
__device__ float g_scores[(size_t)NB * NH * SEQ * SEQ];  // 512 MB
__device__ float g_attno[(size_t)TOK * D];
__device__ float g_h2[(size_t)TOK * D];
__device__ float g_ff[(size_t)TOK * FFD];

// ---------------------------------------------------------------------------
// LayerNorm: one block per row, 288 threads, one float4 per thread
// ---------------------------------------------------------------------------
__global__ void ln_kernel(const float* __restrict__ X, const float* __restrict__ gamma,
                          const float* __restrict__ beta, float* __restrict__ Y) {
    int row = blockIdx.x;
    int tid = threadIdx.x;
    float4 v = ((const float4*)(X + (size_t)row * D))[tid];
    float s  = v.x + v.y + v.z + v.w;
    float sq = v.x * v.x + v.y * v.y + v.z * v.z + v.w * v.w;
    #pragma unroll
    for (int o = 16; o > 0; o >>= 1) {
        s  += __shfl_down_sync(0xffffffffu, s,  o);
        sq += __shfl_down_sync(0xffffffffu, sq, o);
    }
    __shared__ float ss[9], ssq[9];
    int w = tid >> 5, l = tid & 31;
    if (l == 0) { ss[w] = s; ssq[w] = sq; }
    __syncthreads();
    float ts = 0.f, tsq = 0.f;
    #pragma unroll
    for (int i = 0; i < 9; i++) { ts += ss[i]; tsq += ssq[i]; }
    const float invD = 1.0f / (float)D;
    float mean = ts * invD;
    float var  = tsq * invD - mean * mean;
    float rinv = rsqrtf(var + 1e-5f);
    float4 g = ((const float4*)gamma)[tid];
    float4 b = ((const float4*)beta)[tid];
    float4 o;
    o.x = (v.x - mean) * rinv * g.x + b.x;
    o.y = (v.y - mean) * rinv * g.y + b.y;
    o.z = (v.z - mean) * rinv * g.z + b.z;
    o.w = (v.w - mean) * rinv * g.w + b.w;
    ((float4*)(Y + (size_t)row * D))[tid] = o;
}

// ---------------------------------------------------------------------------
// TF32 helpers
// ---------------------------------------------------------------------------
__device__ __forceinline__ float f2tf32(float x) {
    uint32_t r;
    asm("cvt.rna.tf32.f32 %0, %1;" : "=r"(r) : "f"(x));
    return __uint_as_float(r);
}
__device__ __forceinline__ float4 f2tf32_4(float4 v) {
    float4 o;
    o.x = f2tf32(v.x); o.y = f2tf32(v.y); o.z = f2tf32(v.z); o.w = f2tf32(v.w);
    return o;
}
__device__ __forceinline__ void mma_tf32(float* c, uint32_t a0, uint32_t a1,
                                         uint32_t a2, uint32_t a3,
                                         uint32_t b0, uint32_t b1) {
    asm volatile(
        "mma.sync.aligned.m16n8k8.row.col.f32.tf32.tf32.f32 "
        "{%0,%1,%2,%3}, {%4,%5,%6,%7}, {%8,%9}, {%0,%1,%2,%3};\n"
        : "+f"(c[0]), "+f"(c[1]), "+f"(c[2]), "+f"(c[3])
        : "r"(a0), "r"(a1), "r"(a2), "r"(a3), "r"(b0), "r"(b1));
}

// ---------------------------------------------------------------------------
// TF32 tensor-core GEMM: C[M,N] = A[M,K] @ W[K,N] + bias (+GELU) (+res)
// 128x128x16 tile, 8 warps (2x4), warp tile 64x32, double-buffered smem.
// Requires M%128==0, N%128==0, K%16==0.
// ---------------------------------------------------------------------------
#define BM 128
#define BN 128
#define BKT 16
#define BKP 20    // As row pad  -> conflict-free frag loads
#define BNP 136   // Bs row pad  -> conflict-free frag loads

__global__ __launch_bounds__(256, 2)
void sgemm_tf32(const float* __restrict__ A, const float* __restrict__ W,
                const float* __restrict__ bias, const float* __restrict__ res,
                float* __restrict__ C, int M, int N, int K, int gelu_act)
{
    __shared__ __align__(16) float As[2][BM][BKP];
    __shared__ __align__(16) float Bs[2][BKT][BNP];

    int tid  = threadIdx.x;
    int lane = tid & 31;
    int warp = tid >> 5;
    int warpM = warp & 1;          // 2 warps in M
    int warpN = warp >> 1;         // 4 warps in N
    int mwbase = warpM * 64;
    int nwbase = warpN * 32;
    int brow = blockIdx.y * BM;
    int bcol = blockIdx.x * BN;
    int g4 = lane >> 2;            // 0..7
    int t4 = lane & 3;             // 0..3

    // global staging indices
    int a_row = tid >> 2;          // 0..63 (second: +64)
    int a_kq  = (tid & 3) * 4;     // 0,4,8,12
    int w_row = tid >> 5;          // 0..7  (second: +8)
    int w_col = (tid & 31) * 4;

    const float* Aptr  = A + (size_t)(brow + a_row) * K + a_kq;
    const float* Aptr2 = Aptr + (size_t)64 * K;
    const float* Wptr  = W + (size_t)w_row * N + bcol + w_col;
    const float* Wptr2 = Wptr + (size_t)8 * N;

    float acc[4][4][4];
    #pragma unroll
    for (int mt = 0; mt < 4; mt++)
        #pragma unroll
        for (int nt = 0; nt < 4; nt++)
            #pragma unroll
            for (int r = 0; r < 4; r++) acc[mt][nt][r] = 0.f;

    // preload tile 0
    float4 av0 = *(const float4*)(Aptr);
    float4 av1 = *(const float4*)(Aptr2);
    float4 wv0 = *(const float4*)(Wptr);
    float4 wv1 = *(const float4*)(Wptr2);
    *(float4*)&As[0][a_row     ][a_kq] = f2tf32_4(av0);
    *(float4*)&As[0][a_row + 64][a_kq] = f2tf32_4(av1);
    *(float4*)&Bs[0][w_row    ][w_col] = f2tf32_4(wv0);
    *(float4*)&Bs[0][w_row + 8][w_col] = f2tf32_4(wv1);
    __syncthreads();

    int nk = K / BKT;
    for (int kt = 0; kt < nk; kt++) {
        int cur = kt & 1;
        int nxt = cur ^ 1;
        if (kt + 1 < nk) {
            int ko = (kt + 1) * BKT;
            av0 = *(const float4*)(Aptr  + ko);
            av1 = *(const float4*)(Aptr2 + ko);
            wv0 = *(const float4*)(Wptr  + (size_t)ko * N);
            wv1 = *(const float4*)(Wptr2 + (size_t)ko * N);
        }
        #pragma unroll
        for (int kk = 0; kk < BKT; kk += 8) {
            uint32_t b0[4], b1[4];
            #pragma unroll
            for (int nt = 0; nt < 4; nt++) {
                int n = nwbase + nt * 8 + g4;
                b0[nt] = __float_as_uint(Bs[cur][kk + t4    ][n]);
                b1[nt] = __float_as_uint(Bs[cur][kk + 4 + t4][n]);
            }
            #pragma unroll
            for (int mt = 0; mt < 4; mt++) {
                int m = mwbase + mt * 16 + g4;
                uint32_t aa0 = __float_as_uint(As[cur][m    ][kk + t4]);
                uint32_t aa1 = __float_as_uint(As[cur][m + 8][kk + t4]);
                uint32_t aa2 = __float_as_uint(As[cur][m    ][kk + 4 + t4]);
                uint32_t aa3 = __float_as_uint(As[cur][m + 8][kk + 4 + t4]);
                #pragma unroll
                for (int nt = 0; nt < 4; nt++)
                    mma_tf32(acc[mt][nt], aa0, aa1, aa2, aa3, b0[nt], b1[nt]);
            }
        }
        if (kt + 1 < nk) {
            *(float4*)&As[nxt][a_row     ][a_kq] = f2tf32_4(av0);
            *(float4*)&As[nxt][a_row + 64][a_kq] = f2tf32_4(av1);
            *(float4*)&Bs[nxt][w_row    ][w_col] = f2tf32_4(wv0);
            *(float4*)&Bs[nxt][w_row + 8][w_col] = f2tf32_4(wv1);
        }
        __syncthreads();
    }

    // epilogue
    #pragma unroll
    for (int mt = 0; mt < 4; mt++) {
        #pragma unroll
        for (int nt = 0; nt < 4; nt++) {
            int col  = bcol + nwbase + nt * 8 + t4 * 2;
            float bx = bias[col], by = bias[col + 1];
            #pragma unroll
            for (int half = 0; half < 2; half++) {
                size_t row = (size_t)(brow + mwbase + mt * 16 + g4 + half * 8);
                float ox = acc[mt][nt][half * 2 + 0] + bx;
                float oy = acc[mt][nt][half * 2 + 1] + by;
                if (gelu_act) {
                    ox = 0.5f * ox * (1.0f + erff(ox * 0.70710678118f));
                    oy = 0.5f * oy * (1.0f + erff(oy * 0.70710678118f));
                }
                if (res) {
                    const float2 r = *(const float2*)(res + row * N + col);
                    ox += r.x; oy += r.y;
                }
                float2 o; o.x = ox; o.y = oy;
                *(float2*)(C + row * N + col) = o;
            }
        }
    }
}

// ---------------------------------------------------------------------------
// Scores: S[b,h,i,j] = scale * sum_d Q[b,i,h,d] * K[b,j,h,d]
// ---------------------------------------------------------------------------
__global__ void scores_kernel(const float* __restrict__ Q, const float* __restrict__ Km,
                              float* __restrict__ S) {
    int bh = blockIdx.z;
    int b = bh >> 4, h = bh & 15;
    int row0 = blockIdx.y * 64;
    int col0 = blockIdx.x * 64;
    const float* qbase = Q + (size_t)b * SEQ * D + h * HD;
    const float* kbase = Km + (size_t)b * SEQ * D + h * HD;
    __shared__ float Qs[64][76];
    __shared__ float Ks[64][76];
    int tid = threadIdx.x;   // 256
    for (int i = tid; i < 64 * 72; i += 256) {
        int r = i / 72, c = i % 72;
        Qs[r][c] = qbase[(size_t)(row0 + r) * D + c];
        Ks[r][c] = kbase[(size_t)(col0 + r) * D + c];
    }
    __syncthreads();
    int tx = tid & 15, ty = tid >> 4;
    float acc[4][4] = {};
    #pragma unroll 6
    for (int d = 0; d < 72; d += 4) {
        float qr[4][4], kr[4][4];
        #pragma unroll
        for (int i = 0; i < 4; i++) {
            float4 t = *(const float4*)&Qs[ty * 4 + i][d];
            qr[i][0] = t.x; qr[i][1] = t.y; qr[i][2] = t.z; qr[i][3] = t.w;
        }
        #pragma unroll
        for (int j = 0; j < 4; j++) {
            float4 t = *(const float4*)&Ks[tx * 4 + j][d];
            kr[j][0] = t.x; kr[j][1] = t.y; kr[j][2] = t.z; kr[j][3] = t.w;
        }
        #pragma unroll
        for (int t = 0; t < 4; t++)
            #pragma unroll
            for (int i = 0; i < 4; i++)
                #pragma unroll
                for (int j = 0; j < 4; j++)
                    acc[i][j] = fmaf(qr[i][t], kr[j][t], acc[i][j]);
    }
    const float scale = 0.117851130198f;   // 72^-0.5
    float* sbase = S + (size_t)bh * SEQ * SEQ;
    #pragma unroll
    for (int i = 0; i < 4; i++) {
        float4 o;
        o.x = acc[i][0] * scale; o.y = acc[i][1] * scale;
        o.z = acc[i][2] * scale; o.w = acc[i][3] * scale;
        *(float4*)(sbase + (size_t)(row0 + ty * 4 + i) * SEQ + col0 + tx * 4) = o;
    }
}

// ---------------------------------------------------------------------------
// Softmax over last dim (1024). One block per row, 256 threads, float4 each.
// ---------------------------------------------------------------------------
__global__ void softmax_kernel(float* __restrict__ S) {
    float* p = S + (size_t)blockIdx.x * SEQ;
    int tid = threadIdx.x;
    float4 v = ((float4*)p)[tid];
    float m = fmaxf(fmaxf(v.x, v.y), fmaxf(v.z, v.w));
    #pragma unroll
    for (int o = 16; o > 0; o >>= 1) m = fmaxf(m, __shfl_xor_sync(0xffffffffu, m, o));
    __shared__ float sm[8], ssum[8];
    int w = tid >> 5, l = tid & 31;
    if (l == 0) sm[w] = m;
    __syncthreads();
    float M = fmaxf(fmaxf(fmaxf(sm[0], sm[1]), fmaxf(sm[2], sm[3])),
                    fmaxf(fmaxf(sm[4], sm[5]), fmaxf(sm[6], sm[7])));
    v.x = __expf(v.x - M);
    v.y = __expf(v.y - M);
    v.z = __expf(v.z - M);
    v.w = __expf(v.w - M);
    float s = v.x + v.y + v.z + v.w;
    #pragma unroll
    for (int o = 16; o > 0; o >>= 1) s += __shfl_xor_sync(0xffffffffu, s, o);
    if (l == 0) ssum[w] = s;
    __syncthreads();
    float T = ((ssum[0] + ssum[1]) + (ssum[2] + ssum[3])) +
              ((ssum[4] + ssum[5]) + (ssum[6] + ssum[7]));
    float inv = 1.0f / T;
    v.x *= inv; v.y *= inv; v.z *= inv; v.w *= inv;
    ((float4*)p)[tid] = v;
}

// ---------------------------------------------------------------------------
// PV: O[b,i,h,:] = sum_j P[b,h,i,j] * V[b,j,h,:]
// ---------------------------------------------------------------------------
__global__ void av_kernel(const float* __restrict__ P, const float* __restrict__ V,
                          float* __restrict__ O) {
    int bh = blockIdx.y;
    int b = bh >> 4, h = bh & 15;
    int row0 = blockIdx.x * 64;
    const float* pbase = P + (size_t)bh * SEQ * SEQ;
    const float* vbase = V + (size_t)b * SEQ * D + h * HD;
    __shared__ float Ps[64][36];
    __shared__ float Vs[32][76];
    int tid = threadIdx.x;        // 288
    int tx = tid % 18;
    int ty = tid / 18;
    float acc[4][4] = {};
    for (int k0 = 0; k0 < SEQ; k0 += 32) {
        for (int i = tid; i < 64 * 32; i += 288) {
            int r = i >> 5, c = i & 31;
            Ps[r][c] = pbase[(size_t)(row0 + r) * SEQ + k0 + c];
        }
        for (int i = tid; i < 32 * 72; i += 288) {
            int r = i / 72, c = i % 72;
            Vs[r][c] = vbase[(size_t)(k0 + r) * D + c];
        }
        __syncthreads();
        #pragma unroll 8
        for (int kk = 0; kk < 32; kk += 4) {
            float pr[4][4];
            #pragma unroll
            for (int i = 0; i < 4; i++) {
                float4 t = *(const float4*)&Ps[ty * 4 + i][kk];
                pr[i][0] = t.x; pr[i][1] = t.y; pr[i][2] = t.z; pr[i][3] = t.w;
            }
            #pragma unroll
            for (int t = 0; t < 4; t++) {
                float4 vv = *(const float4*)&Vs[kk + t][tx * 4];
                #pragma unroll
                for (int i = 0; i < 4; i++) {
                    acc[i][0] = fmaf(pr[i][t], vv.x, acc[i][0]);
                    acc[i][1] = fmaf(pr[i][t], vv.y, acc[i][1]);
                    acc[i][2] = fmaf(pr[i][t], vv.z, acc[i][2]);
                    acc[i][3] = fmaf(pr[i][t], vv.w, acc[i][3]);
                }
            }
        }
        __syncthreads();
    }
    #pragma unroll
    for (int i = 0; i < 4; i++) {
        size_t row = (size_t)b * SEQ + row0 + ty * 4 + i;
        float4 o;
        o.x = acc[i][0]; o.y = acc[i][1]; o.z = acc[i][2]; o.w = acc[i][3];
        *(float4*)(O + row * D + h * HD + tx * 4) = o;
    }
}

// ---------------------------------------------------------------------------
// Launch
// ---------------------------------------------------------------------------
extern "C" void kernel_launch(void* const* d_in, const int* in_sizes, int n_in,
                              void* d_out, int out_size) {
    const float* hs    = (const float*)d_in[0];
    const float* ln1_w = (const float*)d_in[1];
    const float* ln1_b = (const float*)d_in[2];
    const float* q_w   = (const float*)d_in[3];
    const float* q_b   = (const float*)d_in[4];
    const float* k_w   = (const float*)d_in[5];
    const float* k_b   = (const float*)d_in[6];
    const float* v_w   = (const float*)d_in[7];
    const float* v_b   = (const float*)d_in[8];
    const float* o_w   = (const float*)d_in[9];
    const float* o_b   = (const float*)d_in[10];
    const float* ln2_w = (const float*)d_in[11];
    const float* ln2_b = (const float*)d_in[12];
    const float* fc1_w = (const float*)d_in[13];
    const float* fc1_b = (const float*)d_in[14];
    const float* fc2_w = (const float*)d_in[15];
    const float* fc2_b = (const float*)d_in[16];
    float* out = (float*)d_out;

    float *xln, *q, *k, *v, *sc, *ao, *h2, *ff;
    cudaGetSymbolAddress((void**)&xln, g_xln);
    cudaGetSymbolAddress((void**)&q,   g_q);
    cudaGetSymbolAddress((void**)&k,   g_k);
    cudaGetSymbolAddress((void**)&v,   g_v);
    cudaGetSymbolAddress((void**)&sc,  g_scores);
    cudaGetSymbolAddress((void**)&ao,  g_attno);
    cudaGetSymbolAddress((void**)&h2,  g_h2);
    cudaGetSymbolAddress((void**)&ff,  g_ff);

    dim3 gD(D / 128, TOK / 128);      // (9, 64)
    dim3 gF(FFD / 128, TOK / 128);    // (36, 64)

    // 1. LN1
    ln_kernel<<<TOK, 288>>>(hs, ln1_w, ln1_b, xln);
    // 2. Q, K, V projections (tf32 tensor cores)
    sgemm_tf32<<<gD, 256>>>(xln, q_w, q_b, nullptr, q, TOK, D, D, 0);
    sgemm_tf32<<<gD, 256>>>(xln, k_w, k_b, nullptr, k, TOK, D, D, 0);
    sgemm_tf32<<<gD, 256>>>(xln, v_w, v_b, nullptr, v, TOK, D, D, 0);
    // 3. scores = scale * Q K^T
    scores_kernel<<<dim3(SEQ / 64, SEQ / 64, NB * NH), 256>>>(q, k, sc);
    // 4. softmax
    softmax_kernel<<<NB * NH * SEQ, 256>>>(sc);
    // 5. attn @ V
    av_kernel<<<dim3(SEQ / 64, NB * NH), 288>>>(sc, v, ao);
    // 6. O projection + residual1
    sgemm_tf32<<<gD, 256>>>(ao, o_w, o_b, hs, h2, TOK, D, D, 0);
    // 7. LN2
    ln_kernel<<<TOK, 288>>>(h2, ln2_w, ln2_b, xln);
    // 8. FC1 + exact GELU
    sgemm_tf32<<<gF, 256>>>(xln, fc1_w, fc1_b, nullptr, ff, TOK, FFD, D, 1);
    // 9. FC2 + residual2 -> out
    sgemm_tf32<<<gD, 256>>>(ff, fc2_w, fc2_b, h2, out, TOK, D, FFD, 0);
}

// round 3
// speedup vs baseline: 2.8520x; 1.4463x over previous
#include <cuda_runtime.h>
#include <math.h>
#include <stdint.h>

// Problem dims (fixed by the reference)
#define NB   8
#define SEQ  1024
#define TOK  (NB * SEQ)       // 8192
#define D    1152
#define FFD  4608
#define NH   16
#define HD   72               // head dim

// ---------------------------------------------------------------------------
// Scratch (device globals — no allocations allowed)
// ---------------------------------------------------------------------------
__device__ float g_xln[(size_t)TOK * D];
__device__ float g_q[(size_t)TOK * D];
__device__ float g_k[(size_t)TOK * D];
__device__ float g_v[(size_t)TOK * D];
__device__ float g_scores[(size_t)NB * NH * SEQ * SEQ];  // 512 MB
__device__ float g_attno[(size_t)TOK * D];
__device__ float g_h2[(size_t)TOK * D];
__device__ float g_ff[(size_t)TOK * FFD];

// ---------------------------------------------------------------------------
// LayerNorm
// ---------------------------------------------------------------------------
__global__ void ln_kernel(const float* __restrict__ X, const float* __restrict__ gamma,
                          const float* __restrict__ beta, float* __restrict__ Y) {
    int row = blockIdx.x;
    int tid = threadIdx.x;
    float4 v = ((const float4*)(X + (size_t)row * D))[tid];
    float s  = v.x + v.y + v.z + v.w;
    float sq = v.x * v.x + v.y * v.y + v.z * v.z + v.w * v.w;
    #pragma unroll
    for (int o = 16; o > 0; o >>= 1) {
        s  += __shfl_down_sync(0xffffffffu, s,  o);
        sq += __shfl_down_sync(0xffffffffu, sq, o);
    }
    __shared__ float ss[9], ssq[9];
    int w = tid >> 5, l = tid & 31;
    if (l == 0) { ss[w] = s; ssq[w] = sq; }
    __syncthreads();
    float ts = 0.f, tsq = 0.f;
    #pragma unroll
    for (int i = 0; i < 9; i++) { ts += ss[i]; tsq += ssq[i]; }
    const float invD = 1.0f / (float)D;
    float mean = ts * invD;
    float var  = tsq * invD - mean * mean;
    float rinv = rsqrtf(var + 1e-5f);
    float4 g = ((const float4*)gamma)[tid];
    float4 b = ((const float4*)beta)[tid];
    float4 o;
    o.x = (v.x - mean) * rinv * g.x + b.x;
    o.y = (v.y - mean) * rinv * g.y + b.y;
    o.z = (v.z - mean) * rinv * g.z + b.z;
    o.w = (v.w - mean) * rinv * g.w + b.w;
    ((float4*)(Y + (size_t)row * D))[tid] = o;
}

// ---------------------------------------------------------------------------
// TF32 helpers
// ---------------------------------------------------------------------------
__device__ __forceinline__ float f2tf32(float x) {
    uint32_t r;
    asm("cvt.rna.tf32.f32 %0, %1;" : "=r"(r) : "f"(x));
    return __uint_as_float(r);
}
__device__ __forceinline__ float4 f2tf32_4(float4 v) {
    float4 o;
    o.x = f2tf32(v.x); o.y = f2tf32(v.y); o.z = f2tf32(v.z); o.w = f2tf32(v.w);
    return o;
}
__device__ __forceinline__ void mma_tf32(float* c, uint32_t a0, uint32_t a1,
                                         uint32_t a2, uint32_t a3,
                                         uint32_t b0, uint32_t b1) {
    asm volatile(
        "mma.sync.aligned.m16n8k8.row.col.f32.tf32.tf32.f32 "
        "{%0,%1,%2,%3}, {%4,%5,%6,%7}, {%8,%9}, {%0,%1,%2,%3};\n"
        : "+f"(c[0]), "+f"(c[1]), "+f"(c[2]), "+f"(c[3])
        : "r"(a0), "r"(a1), "r"(a2), "r"(a3), "r"(b0), "r"(b1));
}

// ---------------------------------------------------------------------------
// TF32 tensor-core GEMM: C[M,N] = A[M,K] @ W[K,N] + bias (+GELU) (+res)
// ---------------------------------------------------------------------------
#define BM 128
#define BN 128
#define BKT 16
#define BKP 20    // As row pad
#define BNP 136   // Bs row pad

__global__ __launch_bounds__(256, 2)
void sgemm_tf32(const float* __restrict__ A, const float* __restrict__ W,
                const float* __restrict__ bias, const float* __restrict__ res,
                float* __restrict__ C, int M, int N, int K, int gelu_act)
{
    __shared__ __align__(16) float As[2][BM][BKP];
    __shared__ __align__(16) float Bs[2][BKT][BNP];

    int tid  = threadIdx.x;
    int lane = tid & 31;
    int warp = tid >> 5;
    int warpM = warp & 1;
    int warpN = warp >> 1;
    int mwbase = warpM * 64;
    int nwbase = warpN * 32;
    int brow = blockIdx.y * BM;
    int bcol = blockIdx.x * BN;
    int g4 = lane >> 2;
    int t4 = lane & 3;

    int a_row = tid >> 2;
    int a_kq  = (tid & 3) * 4;
    int w_row = tid >> 5;
    int w_col = (tid & 31) * 4;

    const float* Aptr  = A + (size_t)(brow + a_row) * K + a_kq;
    const float* Aptr2 = Aptr + (size_t)64 * K;
    const float* Wptr  = W + (size_t)w_row * N + bcol + w_col;
    const float* Wptr2 = Wptr + (size_t)8 * N;

    float acc[4][4][4];
    #pragma unroll
    for (int mt = 0; mt < 4; mt++)
        #pragma unroll
        for (int nt = 0; nt < 4; nt++)
            #pragma unroll
            for (int r = 0; r < 4; r++) acc[mt][nt][r] = 0.f;

    float4 av0 = *(const float4*)(Aptr);
    float4 av1 = *(const float4*)(Aptr2);
    float4 wv0 = *(const float4*)(Wptr);
    float4 wv1 = *(const float4*)(Wptr2);
    *(float4*)&As[0][a_row     ][a_kq] = f2tf32_4(av0);
    *(float4*)&As[0][a_row + 64][a_kq] = f2tf32_4(av1);
    *(float4*)&Bs[0][w_row    ][w_col] = f2tf32_4(wv0);
    *(float4*)&Bs[0][w_row + 8][w_col] = f2tf32_4(wv1);
    __syncthreads();

    int nk = K / BKT;
    for (int kt = 0; kt < nk; kt++) {
        int cur = kt & 1;
        int nxt = cur ^ 1;
        if (kt + 1 < nk) {
            int ko = (kt + 1) * BKT;
            av0 = *(const float4*)(Aptr  + ko);
            av1 = *(const float4*)(Aptr2 + ko);
            wv0 = *(const float4*)(Wptr  + (size_t)ko * N);
            wv1 = *(const float4*)(Wptr2 + (size_t)ko * N);
        }
        #pragma unroll
        for (int kk = 0; kk < BKT; kk += 8) {
            uint32_t b0[4], b1[4];
            #pragma unroll
            for (int nt = 0; nt < 4; nt++) {
                int n = nwbase + nt * 8 + g4;
                b0[nt] = __float_as_uint(Bs[cur][kk + t4    ][n]);
                b1[nt] = __float_as_uint(Bs[cur][kk + 4 + t4][n]);
            }
            #pragma unroll
            for (int mt = 0; mt < 4; mt++) {
                int m = mwbase + mt * 16 + g4;
                uint32_t aa0 = __float_as_uint(As[cur][m    ][kk + t4]);
                uint32_t aa1 = __float_as_uint(As[cur][m + 8][kk + t4]);
                uint32_t aa2 = __float_as_uint(As[cur][m    ][kk + 4 + t4]);
                uint32_t aa3 = __float_as_uint(As[cur][m + 8][kk + 4 + t4]);
                #pragma unroll
                for (int nt = 0; nt < 4; nt++)
                    mma_tf32(acc[mt][nt], aa0, aa1, aa2, aa3, b0[nt], b1[nt]);
            }
        }
        if (kt + 1 < nk) {
            *(float4*)&As[nxt][a_row     ][a_kq] = f2tf32_4(av0);
            *(float4*)&As[nxt][a_row + 64][a_kq] = f2tf32_4(av1);
            *(float4*)&Bs[nxt][w_row    ][w_col] = f2tf32_4(wv0);
            *(float4*)&Bs[nxt][w_row + 8][w_col] = f2tf32_4(wv1);
        }
        __syncthreads();
    }

    #pragma unroll
    for (int mt = 0; mt < 4; mt++) {
        #pragma unroll
        for (int nt = 0; nt < 4; nt++) {
            int col  = bcol + nwbase + nt * 8 + t4 * 2;
            float bx = bias[col], by = bias[col + 1];
            #pragma unroll
            for (int half = 0; half < 2; half++) {
                size_t row = (size_t)(brow + mwbase + mt * 16 + g4 + half * 8);
                float ox = acc[mt][nt][half * 2 + 0] + bx;
                float oy = acc[mt][nt][half * 2 + 1] + by;
                if (gelu_act) {
                    ox = 0.5f * ox * (1.0f + erff(ox * 0.70710678118f));
                    oy = 0.5f * oy * (1.0f + erff(oy * 0.70710678118f));
                }
                if (res) {
                    const float2 r = *(const float2*)(res + row * N + col);
                    ox += r.x; oy += r.y;
                }
                float2 o; o.x = ox; o.y = oy;
                *(float2*)(C + row * N + col) = o;
            }
        }
    }
}

// ---------------------------------------------------------------------------
// Scores (tf32 mma): S[b,h,i,j] = scale * sum_d Q[b,i,h,d] * K[b,j,h,d]
// 128x128 tile per block, 256 threads (8 warps, 2x4, warp tile 64x32).
// Dynamic smem: Qs[128][76] + Ks[128][76] = 77,824 B.
// ---------------------------------------------------------------------------
#define SDP 76    // padded head-dim row (conflict-free: 76/4=19, odd*stride pattern)

__global__ __launch_bounds__(256)
void scores_tf32(const float* __restrict__ Q, const float* __restrict__ Km,
                 float* __restrict__ S) {
    extern __shared__ float smem[];
    float (*Qs)[SDP] = (float (*)[SDP])smem;
    float (*Ks)[SDP] = (float (*)[SDP])(smem + 128 * SDP);

    int bh = blockIdx.z;
    int b = bh >> 4, h = bh & 15;
    int row0 = blockIdx.y * 128;
    int col0 = blockIdx.x * 128;
    const float* qbase = Q + (size_t)b * SEQ * D + h * HD;
    const float* kbase = Km + (size_t)b * SEQ * D + h * HD;
    int tid = threadIdx.x;

    // load Q,K tiles (converted to tf32): 128 rows x 72 cols as float2
    for (int i = tid; i < 128 * 36; i += 256) {
        int r = i / 36, c = (i % 36) * 2;
        float2 qv = *(const float2*)(qbase + (size_t)(row0 + r) * D + c);
        Qs[r][c]     = f2tf32(qv.x);
        Qs[r][c + 1] = f2tf32(qv.y);
        float2 kv = *(const float2*)(kbase + (size_t)(col0 + r) * D + c);
        Ks[r][c]     = f2tf32(kv.x);
        Ks[r][c + 1] = f2tf32(kv.y);
    }
    __syncthreads();

    int lane = tid & 31;
    int warp = tid >> 5;
    int warpM = warp & 1;
    int warpN = warp >> 1;
    int mwbase = warpM * 64;
    int nwbase = warpN * 32;
    int g4 = lane >> 2;
    int t4 = lane & 3;

    float acc[4][4][4];
    #pragma unroll
    for (int mt = 0; mt < 4; mt++)
        #pragma unroll
        for (int nt = 0; nt < 4; nt++)
            #pragma unroll
            for (int r = 0; r < 4; r++) acc[mt][nt][r] = 0.f;

    #pragma unroll
    for (int kk = 0; kk < 72; kk += 8) {
        uint32_t b0[4], b1[4];
        #pragma unroll
        for (int nt = 0; nt < 4; nt++) {
            int n = nwbase + nt * 8 + g4;
            b0[nt] = __float_as_uint(Ks[n][kk + t4]);
            b1[nt] = __float_as_uint(Ks[n][kk + 4 + t4]);
        }
        #pragma unroll
        for (int mt = 0; mt < 4; mt++) {
            int m = mwbase + mt * 16 + g4;
            uint32_t aa0 = __float_as_uint(Qs[m    ][kk + t4]);
            uint32_t aa1 = __float_as_uint(Qs[m + 8][kk + t4]);
            uint32_t aa2 = __float_as_uint(Qs[m    ][kk + 4 + t4]);
            uint32_t aa3 = __float_as_uint(Qs[m + 8][kk + 4 + t4]);
            #pragma unroll
            for (int nt = 0; nt < 4; nt++)
                mma_tf32(acc[mt][nt], aa0, aa1, aa2, aa3, b0[nt], b1[nt]);
        }
    }

    const float scale = 0.117851130198f;   // 72^-0.5
    float* sbase = S + (size_t)bh * SEQ * SEQ;
    #pragma unroll
    for (int mt = 0; mt < 4; mt++) {
        #pragma unroll
        for (int nt = 0; nt < 4; nt++) {
            int col = col0 + nwbase + nt * 8 + t4 * 2;
            #pragma unroll
            for (int half = 0; half < 2; half++) {
                size_t row = (size_t)(row0 + mwbase + mt * 16 + g4 + half * 8);
                float2 o;
                o.x = acc[mt][nt][half * 2 + 0] * scale;
                o.y = acc[mt][nt][half * 2 + 1] * scale;
                *(float2*)(sbase + row * SEQ + col) = o;
            }
        }
    }
}

// ---------------------------------------------------------------------------
// Softmax over last dim (1024)
// ---------------------------------------------------------------------------
__global__ void softmax_kernel(float* __restrict__ S) {
    float* p = S + (size_t)blockIdx.x * SEQ;
    int tid = threadIdx.x;
    float4 v = ((float4*)p)[tid];
    float m = fmaxf(fmaxf(v.x, v.y), fmaxf(v.z, v.w));
    #pragma unroll
    for (int o = 16; o > 0; o >>= 1) m = fmaxf(m, __shfl_xor_sync(0xffffffffu, m, o));
    __shared__ float sm[8], ssum[8];
    int w = tid >> 5, l = tid & 31;
    if (l == 0) sm[w] = m;
    __syncthreads();
    float M = fmaxf(fmaxf(fmaxf(sm[0], sm[1]), fmaxf(sm[2], sm[3])),
                    fmaxf(fmaxf(sm[4], sm[5]), fmaxf(sm[6], sm[7])));
    v.x = __expf(v.x - M);
    v.y = __expf(v.y - M);
    v.z = __expf(v.z - M);
    v.w = __expf(v.w - M);
    float s = v.x + v.y + v.z + v.w;
    #pragma unroll
    for (int o = 16; o > 0; o >>= 1) s += __shfl_xor_sync(0xffffffffu, s, o);
    if (l == 0) ssum[w] = s;
    __syncthreads();
    float T = ((ssum[0] + ssum[1]) + (ssum[2] + ssum[3])) +
              ((ssum[4] + ssum[5]) + (ssum[6] + ssum[7]));
    float inv = 1.0f / T;
    v.x *= inv; v.y *= inv; v.z *= inv; v.w *= inv;
    ((float4*)p)[tid] = v;
}

// ---------------------------------------------------------------------------
// PV (tf32 mma): O[b,i,h,:] = sum_j P[b,h,i,j] * V[b,j,h,:]
// Block: 128 rows x 72 cols for one (b,h). 256 threads (8 warps x 16 rows).
// K=1024 in chunks of 16, double-buffered.
// ---------------------------------------------------------------------------
__global__ __launch_bounds__(256)
void av_tf32(const float* __restrict__ P, const float* __restrict__ V,
             float* __restrict__ O) {
    __shared__ __align__(16) float Ps[2][128][20];
    __shared__ __align__(16) float Vs[2][16][SDP];

    int bh = blockIdx.y;
    int b = bh >> 4, h = bh & 15;
    int row0 = blockIdx.x * 128;
    const float* pbase = P + (size_t)bh * SEQ * SEQ;
    const float* vbase = V + (size_t)b * SEQ * D + h * HD;
    int tid = threadIdx.x;
    int lane = tid & 31;
    int warp = tid >> 5;
    int mwbase = warp * 16;
    int g4 = lane >> 4 * 0 + (lane >> 2);   // = lane>>2
    g4 = lane >> 2;
    int t4 = lane & 3;

    // P staging: 128 rows x 16 cols, 2 threads/row (float4 x2 each)
    int p_row = tid >> 1;
    int p_kq  = (tid & 1) * 8;

    float acc[9][4];
    #pragma unroll
    for (int nt = 0; nt < 9; nt++)
        #pragma unroll
        for (int r = 0; r < 4; r++) acc[nt][r] = 0.f;

    // preload stage 0
    {
        float4 pa = *(const float4*)(pbase + (size_t)(row0 + p_row) * SEQ + p_kq);
        float4 pb = *(const float4*)(pbase + (size_t)(row0 + p_row) * SEQ + p_kq + 4);
        *(float4*)&Ps[0][p_row][p_kq]     = f2tf32_4(pa);
        *(float4*)&Ps[0][p_row][p_kq + 4] = f2tf32_4(pb);
        for (int i = tid; i < 16 * 36; i += 256) {
            int r = i / 36, c = (i % 36) * 2;
            float2 vv = *(const float2*)(vbase + (size_t)r * D + c);
            Vs[0][r][c]     = f2tf32(vv.x);
            Vs[0][r][c + 1] = f2tf32(vv.y);
        }
    }
    __syncthreads();

    for (int kt = 0; kt < SEQ / 16; kt++) {
        int cur = kt & 1;
        int nxt = cur ^ 1;
        float4 pa, pb;
        float2 vstage[3];
        int vr[3], vc[3];
        int nv = 0;
        if (kt + 1 < SEQ / 16) {
            int k0 = (kt + 1) * 16;
            pa = *(const float4*)(pbase + (size_t)(row0 + p_row) * SEQ + k0 + p_kq);
            pb = *(const float4*)(pbase + (size_t)(row0 + p_row) * SEQ + k0 + p_kq + 4);
            for (int i = tid; i < 16 * 36; i += 256) {
                int r = i / 36, c = (i % 36) * 2;
                vstage[nv] = *(const float2*)(vbase + (size_t)(k0 + r) * D + c);
                vr[nv] = r; vc[nv] = c; nv++;
            }
        }
        #pragma unroll
        for (int kk = 0; kk < 16; kk += 8) {
            int m = mwbase + g4;
            uint32_t aa0 = __float_as_uint(Ps[cur][m    ][kk + t4]);
            uint32_t aa1 = __float_as_uint(Ps[cur][m + 8][kk + t4]);
            uint32_t aa2 = __float_as_uint(Ps[cur][m    ][kk + 4 + t4]);
            uint32_t aa3 = __float_as_uint(Ps[cur][m + 8][kk + 4 + t4]);
            #pragma unroll
            for (int nt = 0; nt < 9; nt++) {
                int n = nt * 8 + g4;
                uint32_t b0 = __float_as_uint(Vs[cur][kk + t4    ][n]);
                uint32_t b1 = __float_as_uint(Vs[cur][kk + 4 + t4][n]);
                mma_tf32(acc[nt], aa0, aa1, aa2, aa3, b0, b1);
            }
        }
        if (kt + 1 < SEQ / 16) {
            *(float4*)&Ps[nxt][p_row][p_kq]     = f2tf32_4(pa);
            *(float4*)&Ps[nxt][p_row][p_kq + 4] = f2tf32_4(pb);
            for (int i = 0; i < nv; i++) {
                Vs[nxt][vr[i]][vc[i]]     = f2tf32(vstage[i].x);
                Vs[nxt][vr[i]][vc[i] + 1] = f2tf32(vstage[i].y);
            }
        }
        __syncthreads();
    }

    // epilogue: write O[b, row, h*72 + n]
    #pragma unroll
    for (int nt = 0; nt < 9; nt++) {
        int col = h * HD + nt * 8 + t4 * 2;
        #pragma unroll
        for (int half = 0; half < 2; half++) {
            size_t row = (size_t)b * SEQ + row0 + mwbase + g4 + half * 8;
            float2 o;
            o.x = acc[nt][half * 2 + 0];
            o.y = acc[nt][half * 2 + 1];
            *(float2*)(O + row * D + col) = o;
        }
    }
}

// ---------------------------------------------------------------------------
// Launch
// ---------------------------------------------------------------------------
extern "C" void kernel_launch(void* const* d_in, const int* in_sizes, int n_in,
                              void* d_out, int out_size) {
    const float* hs    = (const float*)d_in[0];
    const float* ln1_w = (const float*)d_in[1];
    const float* ln1_b = (const float*)d_in[2];
    const float* q_w   = (const float*)d_in[3];
    const float* q_b   = (const float*)d_in[4];
    const float* k_w   = (const float*)d_in[5];
    const float* k_b   = (const float*)d_in[6];
    const float* v_w   = (const float*)d_in[7];
    const float* v_b   = (const float*)d_in[8];
    const float* o_w   = (const float*)d_in[9];
    const float* o_b   = (const float*)d_in[10];
    const float* ln2_w = (const float*)d_in[11];
    const float* ln2_b = (const float*)d_in[12];
    const float* fc1_w = (const float*)d_in[13];
    const float* fc1_b = (const float*)d_in[14];
    const float* fc2_w = (const float*)d_in[15];
    const float* fc2_b = (const float*)d_in[16];
    float* out = (float*)d_out;

    float *xln, *q, *k, *v, *sc, *ao, *h2, *ff;
    cudaGetSymbolAddress((void**)&xln, g_xln);
    cudaGetSymbolAddress((void**)&q,   g_q);
    cudaGetSymbolAddress((void**)&k,   g_k);
    cudaGetSymbolAddress((void**)&v,   g_v);
    cudaGetSymbolAddress((void**)&sc,  g_scores);
    cudaGetSymbolAddress((void**)&ao,  g_attno);
    cudaGetSymbolAddress((void**)&h2,  g_h2);
    cudaGetSymbolAddress((void**)&ff,  g_ff);

    // scores_tf32 needs 77,824 B dynamic smem (>48KB default)
    static int smem_set = 0;
    const int SCORES_SMEM = 2 * 128 * SDP * 4;
    cudaFuncSetAttribute(scores_tf32, cudaFuncAttributeMaxDynamicSharedMemorySize,
                         SCORES_SMEM);

    dim3 gD(D / 128, TOK / 128);      // (9, 64)
    dim3 gF(FFD / 128, TOK / 128);    // (36, 64)

    // 1. LN1
    ln_kernel<<<TOK, 288>>>(hs, ln1_w, ln1_b, xln);
    // 2. Q, K, V projections (tf32 tensor cores)
    sgemm_tf32<<<gD, 256>>>(xln, q_w, q_b, nullptr, q, TOK, D, D, 0);
    sgemm_tf32<<<gD, 256>>>(xln, k_w, k_b, nullptr, k, TOK, D, D, 0);
    sgemm_tf32<<<gD, 256>>>(xln, v_w, v_b, nullptr, v, TOK, D, D, 0);
    // 3. scores = scale * Q K^T  (tf32 mma)
    scores_tf32<<<dim3(SEQ / 128, SEQ / 128, NB * NH), 256, SCORES_SMEM>>>(q, k, sc);
    // 4. softmax
    softmax_kernel<<<NB * NH * SEQ, 256>>>(sc);
    // 5. attn @ V  (tf32 mma)
    av_tf32<<<dim3(SEQ / 128, NB * NH), 256>>>(sc, v, ao);
    // 6. O projection + residual1
    sgemm_tf32<<<gD, 256>>>(ao, o_w, o_b, hs, h2, TOK, D, D, 0);
    // 7. LN2
    ln_kernel<<<TOK, 288>>>(h2, ln2_w, ln2_b, xln);
    // 8. FC1 + exact GELU
    sgemm_tf32<<<gF, 256>>>(xln, fc1_w, fc1_b, nullptr, ff, TOK, FFD, D, 1);
    // 9. FC2 + residual2 -> out
    sgemm_tf32<<<gD, 256>>>(ff, fc2_w, fc2_b, h2, out, TOK, D, FFD, 0);
    (void)smem_set;
}

// round 4
// speedup vs baseline: 3.8099x; 1.3359x over previous
#include <cuda_runtime.h>
#include <cuda_fp16.h>
#include <math.h>
#include <stdint.h>

// Problem dims (fixed by the reference)
#define NB   8
#define SEQ  1024
#define TOK  (NB * SEQ)       // 8192
#define D    1152
#define FFD  4608
#define NH   16
#define HD   72               // head dim

// ---------------------------------------------------------------------------
// Scratch (device globals — no allocations allowed)
// ---------------------------------------------------------------------------
__device__ float  g_xln[(size_t)TOK * D];
__device__ float  g_q[(size_t)TOK * D];
__device__ float  g_k[(size_t)TOK * D];
__device__ float  g_v[(size_t)TOK * D];
__device__ __half g_scores[(size_t)NB * NH * SEQ * SEQ];  // 256 MB (fp16)
__device__ float  g_attno[(size_t)TOK * D];
__device__ float  g_h2[(size_t)TOK * D];
__device__ float  g_ff[(size_t)TOK * FFD];

// ---------------------------------------------------------------------------
// LayerNorm
// ---------------------------------------------------------------------------
__global__ void ln_kernel(const float* __restrict__ X, const float* __restrict__ gamma,
                          const float* __restrict__ beta, float* __restrict__ Y) {
    int row = blockIdx.x;
    int tid = threadIdx.x;
    float4 v = ((const float4*)(X + (size_t)row * D))[tid];
    float s  = v.x + v.y + v.z + v.w;
    float sq = v.x * v.x + v.y * v.y + v.z * v.z + v.w * v.w;
    #pragma unroll
    for (int o = 16; o > 0; o >>= 1) {
        s  += __shfl_down_sync(0xffffffffu, s,  o);
        sq += __shfl_down_sync(0xffffffffu, sq, o);
    }
    __shared__ float ss[9], ssq[9];
    int w = tid >> 5, l = tid & 31;
    if (l == 0) { ss[w] = s; ssq[w] = sq; }
    __syncthreads();
    float ts = 0.f, tsq = 0.f;
    #pragma unroll
    for (int i = 0; i < 9; i++) { ts += ss[i]; tsq += ssq[i]; }
    const float invD = 1.0f / (float)D;
    float mean = ts * invD;
    float var  = tsq * invD - mean * mean;
    float rinv = rsqrtf(var + 1e-5f);
    float4 g = ((const float4*)gamma)[tid];
    float4 b = ((const float4*)beta)[tid];
    float4 o;
    o.x = (v.x - mean) * rinv * g.x + b.x;
    o.y = (v.y - mean) * rinv * g.y + b.y;
    o.z = (v.z - mean) * rinv * g.z + b.z;
    o.w = (v.w - mean) * rinv * g.w + b.w;
    ((float4*)(Y + (size_t)row * D))[tid] = o;
}

// ---------------------------------------------------------------------------
// fp16 mma helpers
// ---------------------------------------------------------------------------
__device__ __forceinline__ uint32_t smem_u32(const void* p) {
    return (uint32_t)__cvta_generic_to_shared(p);
}
__device__ __forceinline__ void ldsm_x4(uint32_t* r, uint32_t addr) {
    asm volatile("ldmatrix.sync.aligned.m8n8.x4.shared.b16 {%0,%1,%2,%3}, [%4];"
                 : "=r"(r[0]), "=r"(r[1]), "=r"(r[2]), "=r"(r[3]) : "r"(addr));
}
__device__ __forceinline__ void ldsm_x4_t(uint32_t* r, uint32_t addr) {
    asm volatile("ldmatrix.sync.aligned.m8n8.x4.trans.shared.b16 {%0,%1,%2,%3}, [%4];"
                 : "=r"(r[0]), "=r"(r[1]), "=r"(r[2]), "=r"(r[3]) : "r"(addr));
}
__device__ __forceinline__ void mma_f16(float* c, const uint32_t* a,
                                        uint32_t b0, uint32_t b1) {
    asm volatile(
        "mma.sync.aligned.m16n8k16.row.col.f32.f16.f16.f32 "
        "{%0,%1,%2,%3}, {%4,%5,%6,%7}, {%8,%9}, {%0,%1,%2,%3};\n"
        : "+f"(c[0]), "+f"(c[1]), "+f"(c[2]), "+f"(c[3])
        : "r"(a[0]), "r"(a[1]), "r"(a[2]), "r"(a[3]), "r"(b0), "r"(b1));
}
__device__ __forceinline__ uint2 f4_to_h4(float4 v) {
    __half2 lo = __floats2half2_rn(v.x, v.y);
    __half2 hi = __floats2half2_rn(v.z, v.w);
    uint2 r;
    r.x = *(uint32_t*)&lo;
    r.y = *(uint32_t*)&hi;
    return r;
}

// ---------------------------------------------------------------------------
// fp16 tensor-core GEMM: C[M,N] = A[M,K] @ W[K,N] + bias (+GELU) (+res)
// 128x128x32 tile, 8 warps (2x4), warp tile 64x32, double-buffered smem,
// ldmatrix fragment loads. Requires M%128==0, N%128==0, K%32==0.
// ---------------------------------------------------------------------------
__global__ __launch_bounds__(256, 2)
void gemm_f16(const float* __restrict__ A, const float* __restrict__ W,
              const float* __restrict__ bias, const float* __restrict__ res,
              float* __restrict__ C, int M, int N, int K, int gelu_act)
{
    __shared__ __align__(16) __half As[2][128][40];   // pitch 80B: ldsm conflict-free
    __shared__ __align__(16) __half Bs[2][32][136];   // pitch 272B: ldsm conflict-free

    int tid  = threadIdx.x;
    int lane = tid & 31;
    int warp = tid >> 5;
    int mwbase = (warp & 1) * 64;
    int nwbase = (warp >> 1) * 32;
    int brow = blockIdx.y * 128;
    int bcol = blockIdx.x * 128;
    int g4 = lane >> 2;
    int t4 = lane & 3;

    int a_row = tid >> 1;          // 0..127
    int a_k   = (tid & 1) * 16;    // 0 or 16
    int b_k   = tid >> 3;          // 0..31
    int b_n   = (tid & 7) * 16;    // 0..112

    const float* Ap = A + (size_t)(brow + a_row) * K + a_k;
    const float* Wp = W + (size_t)b_k * N + bcol + b_n;

    float acc[4][4][4];
    #pragma unroll
    for (int mt = 0; mt < 4; mt++)
        #pragma unroll
        for (int nt = 0; nt < 4; nt++)
            #pragma unroll
            for (int r = 0; r < 4; r++) acc[mt][nt][r] = 0.f;

    // stage 0
    {
        uint2 ah0 = f4_to_h4(*(const float4*)(Ap + 0));
        uint2 ah1 = f4_to_h4(*(const float4*)(Ap + 4));
        uint2 ah2 = f4_to_h4(*(const float4*)(Ap + 8));
        uint2 ah3 = f4_to_h4(*(const float4*)(Ap + 12));
        uint2 bh0 = f4_to_h4(*(const float4*)(Wp + 0));
        uint2 bh1 = f4_to_h4(*(const float4*)(Wp + 4));
        uint2 bh2 = f4_to_h4(*(const float4*)(Wp + 8));
        uint2 bh3 = f4_to_h4(*(const float4*)(Wp + 12));
        *(uint4*)&As[0][a_row][a_k]     = make_uint4(ah0.x, ah0.y, ah1.x, ah1.y);
        *(uint4*)&As[0][a_row][a_k + 8] = make_uint4(ah2.x, ah2.y, ah3.x, ah3.y);
        *(uint4*)&Bs[0][b_k][b_n]       = make_uint4(bh0.x, bh0.y, bh1.x, bh1.y);
        *(uint4*)&Bs[0][b_k][b_n + 8]   = make_uint4(bh2.x, bh2.y, bh3.x, bh3.y);
    }
    __syncthreads();

    int nk = K / 32;
    for (int kt = 0; kt < nk; kt++) {
        int cur = kt & 1;
        int nxt = cur ^ 1;
        uint2 ah0, ah1, ah2, ah3, bh0, bh1, bh2, bh3;
        if (kt + 1 < nk) {
            const float* ap = Ap + (kt + 1) * 32;
            const float* wp = Wp + (size_t)(kt + 1) * 32 * N;
            ah0 = f4_to_h4(*(const float4*)(ap + 0));
            ah1 = f4_to_h4(*(const float4*)(ap + 4));
            ah2 = f4_to_h4(*(const float4*)(ap + 8));
            ah3 = f4_to_h4(*(const float4*)(ap + 12));
            bh0 = f4_to_h4(*(const float4*)(wp + 0));
            bh1 = f4_to_h4(*(const float4*)(wp + 4));
            bh2 = f4_to_h4(*(const float4*)(wp + 8));
            bh3 = f4_to_h4(*(const float4*)(wp + 12));
        }
        #pragma unroll
        for (int kk = 0; kk < 32; kk += 16) {
            uint32_t bfr[4][2];
            #pragma unroll
            for (int np = 0; np < 2; np++) {
                int kr = kk + (lane & 7) + ((lane >> 3) & 1) * 8;
                int nc = nwbase + np * 16 + (lane >> 4) * 8;
                uint32_t r[4];
                ldsm_x4_t(r, smem_u32(&Bs[cur][kr][nc]));
                bfr[np * 2][0] = r[0]; bfr[np * 2][1] = r[1];
                bfr[np * 2 + 1][0] = r[2]; bfr[np * 2 + 1][1] = r[3];
            }
            #pragma unroll
            for (int mt = 0; mt < 4; mt++) {
                int ar = mwbase + mt * 16 + (lane & 15);
                int ac = kk + (lane >> 4) * 8;
                uint32_t a[4];
                ldsm_x4(a, smem_u32(&As[cur][ar][ac]));
                #pragma unroll
                for (int nt = 0; nt < 4; nt++)
                    mma_f16(acc[mt][nt], a, bfr[nt][0], bfr[nt][1]);
            }
        }
        if (kt + 1 < nk) {
            *(uint4*)&As[nxt][a_row][a_k]     = make_uint4(ah0.x, ah0.y, ah1.x, ah1.y);
            *(uint4*)&As[nxt][a_row][a_k + 8] = make_uint4(ah2.x, ah2.y, ah3.x, ah3.y);
            *(uint4*)&Bs[nxt][b_k][b_n]       = make_uint4(bh0.x, bh0.y, bh1.x, bh1.y);
            *(uint4*)&Bs[nxt][b_k][b_n + 8]   = make_uint4(bh2.x, bh2.y, bh3.x, bh3.y);
        }
        __syncthreads();
    }

    // epilogue (fragment C layout: c0,c1 at (g4, t4*2), c2,c3 at (g4+8, t4*2))
    #pragma unroll
    for (int mt = 0; mt < 4; mt++) {
        #pragma unroll
        for (int nt = 0; nt < 4; nt++) {
            int col  = bcol + nwbase + nt * 8 + t4 * 2;
            float bx = bias[col], by = bias[col + 1];
            #pragma unroll
            for (int half = 0; half < 2; half++) {
                size_t row = (size_t)(brow + mwbase + mt * 16 + g4 + half * 8);
                float ox = acc[mt][nt][half * 2 + 0] + bx;
                float oy = acc[mt][nt][half * 2 + 1] + by;
                if (gelu_act) {
                    ox = 0.5f * ox * (1.0f + erff(ox * 0.70710678118f));
                    oy = 0.5f * oy * (1.0f + erff(oy * 0.70710678118f));
                }
                if (res) {
                    const float2 r = *(const float2*)(res + row * N + col);
                    ox += r.x; oy += r.y;
                }
                float2 o; o.x = ox; o.y = oy;
                *(float2*)(C + row * N + col) = o;
            }
        }
    }
}

// ---------------------------------------------------------------------------
// Scores (fp16 mma): S[b,h,i,j] = scale * sum_d Q[b,i,h,d] * K[b,j,h,d]
// 128x128 tile per block; K padded 72 -> 80 with zeros. Output fp16.
// ---------------------------------------------------------------------------
__global__ __launch_bounds__(256)
void scores_f16(const float* __restrict__ Q, const float* __restrict__ Km,
                __half* __restrict__ S) {
    __shared__ __align__(16) __half Qs[128][88];   // pitch 176B: conflict-free
    __shared__ __align__(16) __half Ks[128][88];

    int bh = blockIdx.z;
    int b = bh >> 4, h = bh & 15;
    int row0 = blockIdx.y * 128;
    int col0 = blockIdx.x * 128;
    const float* qbase = Q + (size_t)b * SEQ * D + h * HD;
    const float* kbase = Km + (size_t)b * SEQ * D + h * HD;
    int tid = threadIdx.x;

    for (int i = tid; i < 128 * 18; i += 256) {
        int r = i / 18, c = (i % 18) * 4;
        *(uint2*)&Qs[r][c] = f4_to_h4(*(const float4*)(qbase + (size_t)(row0 + r) * D + c));
        *(uint2*)&Ks[r][c] = f4_to_h4(*(const float4*)(kbase + (size_t)(col0 + r) * D + c));
    }
    for (int i = tid; i < 128 * 2; i += 256) {   // zero-pad cols 72..79
        int r = i >> 1, c = 72 + (i & 1) * 4;
        uint2 z = make_uint2(0u, 0u);
        *(uint2*)&Qs[r][c] = z;
        *(uint2*)&Ks[r][c] = z;
    }
    __syncthreads();

    int lane = tid & 31;
    int warp = tid >> 5;
    int mwbase = (warp & 1) * 64;
    int nwbase = (warp >> 1) * 32;
    int g4 = lane >> 2;
    int t4 = lane & 3;

    float acc[4][4][4];
    #pragma unroll
    for (int mt = 0; mt < 4; mt++)
        #pragma unroll
        for (int nt = 0; nt < 4; nt++)
            #pragma unroll
            for (int r = 0; r < 4; r++) acc[mt][nt][r] = 0.f;

    #pragma unroll
    for (int kk = 0; kk < 80; kk += 16) {
        uint32_t bfr[4][2];
        #pragma unroll
        for (int np = 0; np < 2; np++) {
            // B-fragment from row-major K[j][d] via non-trans ldmatrix:
            // m0 = b0(nt), m1 = b1(nt), m2 = b0(nt+1), m3 = b1(nt+1)
            int nr = nwbase + np * 16 + (lane & 7) + (lane >> 4) * 8;
            int nc = kk + ((lane >> 3) & 1) * 8;
            uint32_t r[4];
            ldsm_x4(r, smem_u32(&Ks[nr][nc]));
            bfr[np * 2][0] = r[0]; bfr[np * 2][1] = r[1];
            bfr[np * 2 + 1][0] = r[2]; bfr[np * 2 + 1][1] = r[3];
        }
        #pragma unroll
        for (int mt = 0; mt < 4; mt++) {
            int ar = mwbase + mt * 16 + (lane & 15);
            int ac = kk + (lane >> 4) * 8;
            uint32_t a[4];
            ldsm_x4(a, smem_u32(&Qs[ar][ac]));
            #pragma unroll
            for (int nt = 0; nt < 4; nt++)
                mma_f16(acc[mt][nt], a, bfr[nt][0], bfr[nt][1]);
        }
    }

    const float scale = 0.117851130198f;   // 72^-0.5
    __half* sbase = S + (size_t)bh * SEQ * SEQ;
    #pragma unroll
    for (int mt = 0; mt < 4; mt++) {
        #pragma unroll
        for (int nt = 0; nt < 4; nt++) {
            int col = col0 + nwbase + nt * 8 + t4 * 2;
            int r0_ = row0 + mwbase + mt * 16 + g4;
            __half2 h0 = __floats2half2_rn(acc[mt][nt][0] * scale, acc[mt][nt][1] * scale);
            __half2 h1 = __floats2half2_rn(acc[mt][nt][2] * scale, acc[mt][nt][3] * scale);
            *(__half2*)(sbase + (size_t)r0_ * SEQ + col) = h0;
            *(__half2*)(sbase + (size_t)(r0_ + 8) * SEQ + col) = h1;
        }
    }
}

// ---------------------------------------------------------------------------
// Softmax over last dim (1024), fp16 in/out, fp32 math.
// ---------------------------------------------------------------------------
__global__ void softmax_h(__half* __restrict__ S) {
    __half* p = S + (size_t)blockIdx.x * SEQ;
    int tid = threadIdx.x;
    uint2 u = ((const uint2*)p)[tid];
    __half2 h0 = *(__half2*)&u.x;
    __half2 h1 = *(__half2*)&u.y;
    float2 f0 = __half22float2(h0);
    float2 f1 = __half22float2(h1);
    float m = fmaxf(fmaxf(f0.x, f0.y), fmaxf(f1.x, f1.y));
    #pragma unroll
    for (int o = 16; o > 0; o >>= 1) m = fmaxf(m, __shfl_xor_sync(0xffffffffu, m, o));
    __shared__ float sm[8], ssum[8];
    int w = tid >> 5, l = tid & 31;
    if (l == 0) sm[w] = m;
    __syncthreads();
    float M = fmaxf(fmaxf(fmaxf(sm[0], sm[1]), fmaxf(sm[2], sm[3])),
                    fmaxf(fmaxf(sm[4], sm[5]), fmaxf(sm[6], sm[7])));
    f0.x = __expf(f0.x - M);
    f0.y = __expf(f0.y - M);
    f1.x = __expf(f1.x - M);
    f1.y = __expf(f1.y - M);
    float s = f0.x + f0.y + f1.x + f1.y;
    #pragma unroll
    for (int o = 16; o > 0; o >>= 1) s += __shfl_xor_sync(0xffffffffu, s, o);
    if (l == 0) ssum[w] = s;
    __syncthreads();
    float T = ((ssum[0] + ssum[1]) + (ssum[2] + ssum[3])) +
              ((ssum[4] + ssum[5]) + (ssum[6] + ssum[7]));
    float inv = 1.0f / T;
    __half2 o0 = __floats2half2_rn(f0.x * inv, f0.y * inv);
    __half2 o1 = __floats2half2_rn(f1.x * inv, f1.y * inv);
    uint2 wout;
    wout.x = *(uint32_t*)&o0;
    wout.y = *(uint32_t*)&o1;
    ((uint2*)p)[tid] = wout;
}

// ---------------------------------------------------------------------------
// PV (fp16 mma): O[b,i,h,:] = sum_j P[b,h,i,j] * V[b,j,h,:]
// Block: 128 rows x 72(->80) cols for one (b,h); 8 warps x 16 rows.
// K=1024 in chunks of 32, double-buffered.
// ---------------------------------------------------------------------------
__global__ __launch_bounds__(256)
void av_f16(const __half* __restrict__ P, const float* __restrict__ V,
            float* __restrict__ O) {
    __shared__ __align__(16) __half Ps[2][128][40];
    __shared__ __align__(16) __half Vs[2][32][88];

    int bh = blockIdx.y;
    int b = bh >> 4, h = bh & 15;
    int row0 = blockIdx.x * 128;
    const __half* pbase = P + (size_t)bh * SEQ * SEQ;
    const float* vbase = V + (size_t)b * SEQ * D + h * HD;
    int tid = threadIdx.x;
    int lane = tid & 31;
    int warp = tid >> 5;
    int g4 = lane >> 2;
    int t4 = lane & 3;
    int p_row = tid >> 1;
    int p_k   = (tid & 1) * 16;

    float acc[10][4];
    #pragma unroll
    for (int nt = 0; nt < 10; nt++)
        #pragma unroll
        for (int r = 0; r < 4; r++) acc[nt][r] = 0.f;

    // zero-pad Vs cols 72..79 in BOTH buffers (never overwritten)
    for (int i = tid; i < 128; i += 256) {
        int buf = i >> 6, r = (i & 63) >> 1, c = 72 + (i & 1) * 4;
        *(uint2*)&Vs[buf][r][c] = make_uint2(0u, 0u);
    }
    // stage 0
    {
        const __half* ps = pbase + (size_t)(row0 + p_row) * SEQ + p_k;
        *(uint4*)&Ps[0][p_row][p_k]     = *(const uint4*)(ps);
        *(uint4*)&Ps[0][p_row][p_k + 8] = *(const uint4*)(ps + 8);
        for (int i = tid; i < 32 * 18; i += 256) {
            int r = i / 18, c = (i % 18) * 4;
            *(uint2*)&Vs[0][r][c] = f4_to_h4(*(const float4*)(vbase + (size_t)r * D + c));
        }
    }
    __syncthreads();

    for (int kt = 0; kt < SEQ / 32; kt++) {
        int cur = kt & 1;
        int nxt = cur ^ 1;
        uint4 pu0, pu1;
        uint2 vh[3]; int vr[3], vc[3]; int nv = 0;
        if (kt + 1 < SEQ / 32) {
            int k0 = (kt + 1) * 32;
            const __half* ps = pbase + (size_t)(row0 + p_row) * SEQ + k0 + p_k;
            pu0 = *(const uint4*)(ps);
            pu1 = *(const uint4*)(ps + 8);
            for (int i = tid; i < 32 * 18; i += 256) {
                int r = i / 18, c = (i % 18) * 4;
                vh[nv] = f4_to_h4(*(const float4*)(vbase + (size_t)(k0 + r) * D + c));
                vr[nv] = r; vc[nv] = c; nv++;
            }
        }
        #pragma unroll
        for (int kk = 0; kk < 32; kk += 16) {
            uint32_t a[4];
            int ar = warp * 16 + (lane & 15);
            int ac = kk + (lane >> 4) * 8;
            ldsm_x4(a, smem_u32(&Ps[cur][ar][ac]));
            #pragma unroll
            for (int np = 0; np < 5; np++) {
                int kr = kk + (lane & 7) + ((lane >> 3) & 1) * 8;
                int nc = np * 16 + (lane >> 4) * 8;
                uint32_t r[4];
                ldsm_x4_t(r, smem_u32(&Vs[cur][kr][nc]));
                mma_f16(acc[np * 2],     a, r[0], r[1]);
                mma_f16(acc[np * 2 + 1], a, r[2], r[3]);
            }
        }
        if (kt + 1 < SEQ / 32) {
            *(uint4*)&Ps[nxt][p_row][p_k]     = pu0;
            *(uint4*)&Ps[nxt][p_row][p_k + 8] = pu1;
            for (int i = 0; i < nv; i++)
                *(uint2*)&Vs[nxt][vr[i]][vc[i]] = vh[i];
        }
        __syncthreads();
    }

    // epilogue: write only n < 72
    #pragma unroll
    for (int nt = 0; nt < 9; nt++) {
        int col = h * HD + nt * 8 + t4 * 2;
        size_t r = (size_t)b * SEQ + row0 + warp * 16 + g4;
        *(float2*)(O + r * D + col)       = make_float2(acc[nt][0], acc[nt][1]);
        *(float2*)(O + (r + 8) * D + col) = make_float2(acc[nt][2], acc[nt][3]);
    }
}

// ---------------------------------------------------------------------------
// Launch
// ---------------------------------------------------------------------------
extern "C" void kernel_launch(void* const* d_in, const int* in_sizes, int n_in,
                              void* d_out, int out_size) {
    const float* hs    = (const float*)d_in[0];
    const float* ln1_w = (const float*)d_in[1];
    const float* ln1_b = (const float*)d_in[2];
    const float* q_w   = (const float*)d_in[3];
    const float* q_b   = (const float*)d_in[4];
    const float* k_w   = (const float*)d_in[5];
    const float* k_b   = (const float*)d_in[6];
    const float* v_w   = (const float*)d_in[7];
    const float* v_b   = (const float*)d_in[8];
    const float* o_w   = (const float*)d_in[9];
    const float* o_b   = (const float*)d_in[10];
    const float* ln2_w = (const float*)d_in[11];
    const float* ln2_b = (const float*)d_in[12];
    const float* fc1_w = (const float*)d_in[13];
    const float* fc1_b = (const float*)d_in[14];
    const float* fc2_w = (const float*)d_in[15];
    const float* fc2_b = (const float*)d_in[16];
    float* out = (float*)d_out;

    float *xln, *q, *k, *v, *ao, *h2, *ff;
    __half* sc;
    cudaGetSymbolAddress((void**)&xln, g_xln);
    cudaGetSymbolAddress((void**)&q,   g_q);
    cudaGetSymbolAddress((void**)&k,   g_k);
    cudaGetSymbolAddress((void**)&v,   g_v);
    cudaGetSymbolAddress((void**)&sc,  g_scores);
    cudaGetSymbolAddress((void**)&ao,  g_attno);
    cudaGetSymbolAddress((void**)&h2,  g_h2);
    cudaGetSymbolAddress((void**)&ff,  g_ff);

    dim3 gD(D / 128, TOK / 128);      // (9, 64)
    dim3 gF(FFD / 128, TOK / 128);    // (36, 64)

    // 1. LN1
    ln_kernel<<<TOK, 288>>>(hs, ln1_w, ln1_b, xln);
    // 2. Q, K, V projections (fp16 tensor cores)
    gemm_f16<<<gD, 256>>>(xln, q_w, q_b, nullptr, q, TOK, D, D, 0);
    gemm_f16<<<gD, 256>>>(xln, k_w, k_b, nullptr, k, TOK, D, D, 0);
    gemm_f16<<<gD, 256>>>(xln, v_w, v_b, nullptr, v, TOK, D, D, 0);
    // 3. scores = scale * Q K^T  (fp16 mma, fp16 output)
    scores_f16<<<dim3(SEQ / 128, SEQ / 128, NB * NH), 256>>>(q, k, sc);
    // 4. softmax (fp16 storage)
    softmax_h<<<NB * NH * SEQ, 256>>>(sc);
    // 5. attn @ V  (fp16 mma)
    av_f16<<<dim3(SEQ / 128, NB * NH), 256>>>(sc, v, ao);
    // 6. O projection + residual1
    gemm_f16<<<gD, 256>>>(ao, o_w, o_b, hs, h2, TOK, D, D, 0);
    // 7. LN2
    ln_kernel<<<TOK, 288>>>(h2, ln2_w, ln2_b, xln);
    // 8. FC1 + exact GELU
    gemm_f16<<<gF, 256>>>(xln, fc1_w, fc1_b, nullptr, ff, TOK, FFD, D, 1);
    // 9. FC2 + residual2 -> out
    gemm_f16<<<gD, 256>>>(ff, fc2_w, fc2_b, h2, out, TOK, D, FFD, 0);
}

// round 5
// speedup vs baseline: 5.5015x; 1.4440x over previous
#include <cuda_runtime.h>
#include <cuda_fp16.h>
#include <math.h>
#include <stdint.h>

// Problem dims
#define NB   8
#define SEQ  1024
#define TOK  (NB * SEQ)       // 8192
#define D    1152
#define FFD  4608
#define NH   16
#define HD   72
#define QKVN 3456             // 3*D

// ---------------------------------------------------------------------------
// Scratch (device globals)
// ---------------------------------------------------------------------------
__device__ __half g_xln[(size_t)TOK * D];
__device__ __half g_qkv[(size_t)TOK * QKVN];            // packed Q|K|V (fp16)
__device__ __half g_scores[(size_t)NB * NH * SEQ * SEQ];
__device__ __half g_ao[(size_t)TOK * D];
__device__ float  g_h2[(size_t)TOK * D];
__device__ __half g_ff[(size_t)TOK * FFD];
// fp16 weights (converted once per launch)
__device__ __half g_wqkv[(size_t)D * QKVN];
__device__ float  g_bqkv[QKVN];
__device__ __half g_wo[(size_t)D * D];
__device__ __half g_wfc1[(size_t)D * FFD];
__device__ __half g_wfc2[(size_t)FFD * D];

// ---------------------------------------------------------------------------
// helpers
// ---------------------------------------------------------------------------
__device__ __forceinline__ uint32_t smem_u32(const void* p) {
    return (uint32_t)__cvta_generic_to_shared(p);
}
__device__ __forceinline__ void ldsm_x4(uint32_t* r, uint32_t addr) {
    asm volatile("ldmatrix.sync.aligned.m8n8.x4.shared.b16 {%0,%1,%2,%3}, [%4];"
                 : "=r"(r[0]), "=r"(r[1]), "=r"(r[2]), "=r"(r[3]) : "r"(addr));
}
__device__ __forceinline__ void ldsm_x4_t(uint32_t* r, uint32_t addr) {
    asm volatile("ldmatrix.sync.aligned.m8n8.x4.trans.shared.b16 {%0,%1,%2,%3}, [%4];"
                 : "=r"(r[0]), "=r"(r[1]), "=r"(r[2]), "=r"(r[3]) : "r"(addr));
}
__device__ __forceinline__ void mma_f16(float* c, const uint32_t* a,
                                        uint32_t b0, uint32_t b1) {
    asm volatile(
        "mma.sync.aligned.m16n8k16.row.col.f32.f16.f16.f32 "
        "{%0,%1,%2,%3}, {%4,%5,%6,%7}, {%8,%9}, {%0,%1,%2,%3};\n"
        : "+f"(c[0]), "+f"(c[1]), "+f"(c[2]), "+f"(c[3])
        : "r"(a[0]), "r"(a[1]), "r"(a[2]), "r"(a[3]), "r"(b0), "r"(b1));
}
__device__ __forceinline__ uint2 f4_to_h4(float4 v) {
    __half2 lo = __floats2half2_rn(v.x, v.y);
    __half2 hi = __floats2half2_rn(v.z, v.w);
    uint2 r;
    r.x = *(uint32_t*)&lo;
    r.y = *(uint32_t*)&hi;
    return r;
}
__device__ __forceinline__ void cp16(uint32_t dst, const void* src) {
    asm volatile("cp.async.cg.shared.global [%0], [%1], 16;" :: "r"(dst), "l"(src));
}
__device__ __forceinline__ void cp_commit() {
    asm volatile("cp.async.commit_group;");
}
__device__ __forceinline__ void cp_wait0() {
    asm volatile("cp.async.wait_group 0;");
}

// ---------------------------------------------------------------------------
// Weight conversion / packing (runs every launch; graph-capturable)
// ---------------------------------------------------------------------------
__global__ void pack_qkv(const float* __restrict__ qw, const float* __restrict__ kw,
                         const float* __restrict__ vw, const float* __restrict__ qb,
                         const float* __restrict__ kb, const float* __restrict__ vb,
                         __half* __restrict__ w16, float* __restrict__ b) {
    int idx = blockIdx.x * blockDim.x + threadIdx.x;
    int e = idx * 4;
    if (e < D * D) {
        int k = e / D, n = e % D;
        size_t o = (size_t)k * QKVN + n;
        *(uint2*)&w16[o]        = f4_to_h4(*(const float4*)(qw + e));
        *(uint2*)&w16[o + 1152] = f4_to_h4(*(const float4*)(kw + e));
        *(uint2*)&w16[o + 2304] = f4_to_h4(*(const float4*)(vw + e));
    }
    if (idx < D) {
        b[idx]        = qb[idx];
        b[idx + 1152] = kb[idx];
        b[idx + 2304] = vb[idx];
    }
}
__global__ void conv_h(const float* __restrict__ src, __half* __restrict__ dst, int n4) {
    int i = blockIdx.x * blockDim.x + threadIdx.x;
    if (i < n4)
        *(uint2*)&dst[(size_t)i * 4] = f4_to_h4(*(const float4*)(src + (size_t)i * 4));
}

// ---------------------------------------------------------------------------
// LayerNorm: fp32 in, fp16 out
// ---------------------------------------------------------------------------
__global__ void ln_kernel(const float* __restrict__ X, const float* __restrict__ gamma,
                          const float* __restrict__ beta, __half* __restrict__ Y) {
    int row = blockIdx.x;
    int tid = threadIdx.x;
    float4 v = ((const float4*)(X + (size_t)row * D))[tid];
    float s  = v.x + v.y + v.z + v.w;
    float sq = v.x * v.x + v.y * v.y + v.z * v.z + v.w * v.w;
    #pragma unroll
    for (int o = 16; o > 0; o >>= 1) {
        s  += __shfl_down_sync(0xffffffffu, s,  o);
        sq += __shfl_down_sync(0xffffffffu, sq, o);
    }
    __shared__ float ss[9], ssq[9];
    int w = tid >> 5, l = tid & 31;
    if (l == 0) { ss[w] = s; ssq[w] = sq; }
    __syncthreads();
    float ts = 0.f, tsq = 0.f;
    #pragma unroll
    for (int i = 0; i < 9; i++) { ts += ss[i]; tsq += ssq[i]; }
    const float invD = 1.0f / (float)D;
    float mean = ts * invD;
    float var  = tsq * invD - mean * mean;
    float rinv = rsqrtf(var + 1e-5f);
    float4 g = ((const float4*)gamma)[tid];
    float4 b = ((const float4*)beta)[tid];
    float4 o;
    o.x = (v.x - mean) * rinv * g.x + b.x;
    o.y = (v.y - mean) * rinv * g.y + b.y;
    o.z = (v.z - mean) * rinv * g.z + b.z;
    o.w = (v.w - mean) * rinv * g.w + b.w;
    *(uint2*)(Y + (size_t)row * D + tid * 4) = f4_to_h4(o);
}

// ---------------------------------------------------------------------------
// fp16 GEMM with cp.async staging.
// C[M,N] = A[M,K](fp16, row stride lda) @ W[K,N](fp16) + bias (+GELU) (+res)
// 128x128x32 tile, 8 warps (2x4), warp tile 64x32, double buffer.
// ---------------------------------------------------------------------------
__global__ __launch_bounds__(256, 2)
void gemm_h(const __half* __restrict__ A, const __half* __restrict__ W,
            const float* __restrict__ bias, const float* __restrict__ res,
            void* __restrict__ Cv, int M, int N, int K, int lda,
            int gelu_act, int out_half)
{
    __shared__ __align__(16) __half As[2][128][40];
    __shared__ __align__(16) __half Bs[2][32][136];

    int tid  = threadIdx.x;
    int lane = tid & 31;
    int warp = tid >> 5;
    int mwbase = (warp & 1) * 64;
    int nwbase = (warp >> 1) * 32;
    int brow = blockIdx.y * 128;
    int bcol = blockIdx.x * 128;
    int g4 = lane >> 2;
    int t4 = lane & 3;

    // cp.async staging indices
    int a_row = tid >> 1;            // 0..127
    int a_c   = (tid & 1) * 16;      // halves: 0 / 16 ; two chunks (+0, +8)
    int b_row = tid >> 3;            // 0..31
    int b_c   = (tid & 7) * 16;      // halves: 0..112 ; two chunks (+0, +8)

    const __half* Ap = A + (size_t)(brow + a_row) * lda + a_c;
    const __half* Wp = W + (size_t)b_row * N + bcol + b_c;

    float acc[4][4][4];
    #pragma unroll
    for (int mt = 0; mt < 4; mt++)
        #pragma unroll
        for (int nt = 0; nt < 4; nt++)
            #pragma unroll
            for (int r = 0; r < 4; r++) acc[mt][nt][r] = 0.f;

    // preload stage 0
    cp16(smem_u32(&As[0][a_row][a_c]),     Ap);
    cp16(smem_u32(&As[0][a_row][a_c + 8]), Ap + 8);
    cp16(smem_u32(&Bs[0][b_row][b_c]),     Wp);
    cp16(smem_u32(&Bs[0][b_row][b_c + 8]), Wp + 8);
    cp_commit();
    cp_wait0();
    __syncthreads();

    int nk = K / 32;
    for (int kt = 0; kt < nk; kt++) {
        int cur = kt & 1;
        int nxt = cur ^ 1;
        if (kt + 1 < nk) {
            const __half* ap = Ap + (kt + 1) * 32;
            const __half* wp = Wp + (size_t)(kt + 1) * 32 * N;
            cp16(smem_u32(&As[nxt][a_row][a_c]),     ap);
            cp16(smem_u32(&As[nxt][a_row][a_c + 8]), ap + 8);
            cp16(smem_u32(&Bs[nxt][b_row][b_c]),     wp);
            cp16(smem_u32(&Bs[nxt][b_row][b_c + 8]), wp + 8);
            cp_commit();
        }
        #pragma unroll
        for (int kk = 0; kk < 32; kk += 16) {
            uint32_t bfr[4][2];
            #pragma unroll
            for (int np = 0; np < 2; np++) {
                int kr = kk + (lane & 7) + ((lane >> 3) & 1) * 8;
                int nc = nwbase + np * 16 + (lane >> 4) * 8;
                uint32_t r[4];
                ldsm_x4_t(r, smem_u32(&Bs[cur][kr][nc]));
                bfr[np * 2][0] = r[0]; bfr[np * 2][1] = r[1];
                bfr[np * 2 + 1][0] = r[2]; bfr[np * 2 + 1][1] = r[3];
            }
            #pragma unroll
            for (int mt = 0; mt < 4; mt++) {
                int ar = mwbase + mt * 16 + (lane & 15);
                int ac = kk + (lane >> 4) * 8;
                uint32_t a[4];
                ldsm_x4(a, smem_u32(&As[cur][ar][ac]));
                #pragma unroll
                for (int nt = 0; nt < 4; nt++)
                    mma_f16(acc[mt][nt], a, bfr[nt][0], bfr[nt][1]);
            }
        }
        if (kt + 1 < nk) cp_wait0();
        __syncthreads();
    }

    // epilogue
    #pragma unroll
    for (int mt = 0; mt < 4; mt++) {
        #pragma unroll
        for (int nt = 0; nt < 4; nt++) {
            int col  = bcol + nwbase + nt * 8 + t4 * 2;
            float bx = bias[col], by = bias[col + 1];
            #pragma unroll
            for (int half = 0; half < 2; half++) {
                size_t row = (size_t)(brow + mwbase + mt * 16 + g4 + half * 8);
                float ox = acc[mt][nt][half * 2 + 0] + bx;
                float oy = acc[mt][nt][half * 2 + 1] + by;
                if (gelu_act) {
                    ox = 0.5f * ox * (1.0f + erff(ox * 0.70710678118f));
                    oy = 0.5f * oy * (1.0f + erff(oy * 0.70710678118f));
                }
                if (out_half) {
                    __half* Ch = (__half*)Cv;
                    *(__half2*)(Ch + row * N + col) = __floats2half2_rn(ox, oy);
                } else {
                    if (res) {
                        const float2 r = *(const float2*)(res + row * N + col);
                        ox += r.x; oy += r.y;
                    }
                    *(float2*)((float*)Cv + row * N + col) = make_float2(ox, oy);
                }
            }
        }
    }
}

// ---------------------------------------------------------------------------
// Scores (fp16 mma): reads Q,K from packed QKV (fp16), output fp16.
// ---------------------------------------------------------------------------
__global__ __launch_bounds__(256)
void scores_f16(const __half* __restrict__ QKV, __half* __restrict__ S) {
    __shared__ __align__(16) __half Qs[128][88];
    __shared__ __align__(16) __half Ks[128][88];

    int bh = blockIdx.z;
    int b = bh >> 4, h = bh & 15;
    int row0 = blockIdx.y * 128;
    int col0 = blockIdx.x * 128;
    const __half* qbase = QKV + (size_t)b * SEQ * QKVN + h * HD;
    const __half* kbase = qbase + 1152;
    int tid = threadIdx.x;

    for (int i = tid; i < 128 * 18; i += 256) {
        int r = i / 18, c = (i % 18) * 4;
        *(uint2*)&Qs[r][c] = *(const uint2*)(qbase + (size_t)(row0 + r) * QKVN + c);
        *(uint2*)&Ks[r][c] = *(const uint2*)(kbase + (size_t)(col0 + r) * QKVN + c);
    }
    for (int i = tid; i < 128 * 2; i += 256) {
        int r = i >> 1, c = 72 + (i & 1) * 4;
        uint2 z = make_uint2(0u, 0u);
        *(uint2*)&Qs[r][c] = z;
        *(uint2*)&Ks[r][c] = z;
    }
    __syncthreads();

    int lane = tid & 31;
    int warp = tid >> 5;
    int mwbase = (warp & 1) * 64;
    int nwbase = (warp >> 1) * 32;
    int g4 = lane >> 2;
    int t4 = lane & 3;

    float acc[4][4][4];
    #pragma unroll
    for (int mt = 0; mt < 4; mt++)
        #pragma unroll
        for (int nt = 0; nt < 4; nt++)
            #pragma unroll
            for (int r = 0; r < 4; r++) acc[mt][nt][r] = 0.f;

    #pragma unroll
    for (int kk = 0; kk < 80; kk += 16) {
        uint32_t bfr[4][2];
        #pragma unroll
        for (int np = 0; np < 2; np++) {
            int nr = nwbase + np * 16 + (lane & 7) + (lane >> 4) * 8;
            int nc = kk + ((lane >> 3) & 1) * 8;
            uint32_t r[4];
            ldsm_x4(r, smem_u32(&Ks[nr][nc]));
            bfr[np * 2][0] = r[0]; bfr[np * 2][1] = r[1];
            bfr[np * 2 + 1][0] = r[2]; bfr[np * 2 + 1][1] = r[3];
        }
        #pragma unroll
        for (int mt = 0; mt < 4; mt++) {
            int ar = mwbase + mt * 16 + (lane & 15);
            int ac = kk + (lane >> 4) * 8;
            uint32_t a[4];
            ldsm_x4(a, smem_u32(&Qs[ar][ac]));
            #pragma unroll
            for (int nt = 0; nt < 4; nt++)
                mma_f16(acc[mt][nt], a, bfr[nt][0], bfr[nt][1]);
        }
    }

    const float scale = 0.117851130198f;
    __half* sbase = S + (size_t)bh * SEQ * SEQ;
    #pragma unroll
    for (int mt = 0; mt < 4; mt++) {
        #pragma unroll
        for (int nt = 0; nt < 4; nt++) {
            int col = col0 + nwbase + nt * 8 + t4 * 2;
            int r0_ = row0 + mwbase + mt * 16 + g4;
            __half2 h0 = __floats2half2_rn(acc[mt][nt][0] * scale, acc[mt][nt][1] * scale);
            __half2 h1 = __floats2half2_rn(acc[mt][nt][2] * scale, acc[mt][nt][3] * scale);
            *(__half2*)(sbase + (size_t)r0_ * SEQ + col) = h0;
            *(__half2*)(sbase + (size_t)(r0_ + 8) * SEQ + col) = h1;
        }
    }
}

// ---------------------------------------------------------------------------
// Softmax (fp16 storage, fp32 math)
// ---------------------------------------------------------------------------
__global__ void softmax_h(__half* __restrict__ S) {
    __half* p = S + (size_t)blockIdx.x * SEQ;
    int tid = threadIdx.x;
    uint2 u = ((const uint2*)p)[tid];
    __half2 h0 = *(__half2*)&u.x;
    __half2 h1 = *(__half2*)&u.y;
    float2 f0 = __half22float2(h0);
    float2 f1 = __half22float2(h1);
    float m = fmaxf(fmaxf(f0.x, f0.y), fmaxf(f1.x, f1.y));
    #pragma unroll
    for (int o = 16; o > 0; o >>= 1) m = fmaxf(m, __shfl_xor_sync(0xffffffffu, m, o));
    __shared__ float sm[8], ssum[8];
    int w = tid >> 5, l = tid & 31;
    if (l == 0) sm[w] = m;
    __syncthreads();
    float M = fmaxf(fmaxf(fmaxf(sm[0], sm[1]), fmaxf(sm[2], sm[3])),
                    fmaxf(fmaxf(sm[4], sm[5]), fmaxf(sm[6], sm[7])));
    f0.x = __expf(f0.x - M);
    f0.y = __expf(f0.y - M);
    f1.x = __expf(f1.x - M);
    f1.y = __expf(f1.y - M);
    float s = f0.x + f0.y + f1.x + f1.y;
    #pragma unroll
    for (int o = 16; o > 0; o >>= 1) s += __shfl_xor_sync(0xffffffffu, s, o);
    if (l == 0) ssum[w] = s;
    __syncthreads();
    float T = ((ssum[0] + ssum[1]) + (ssum[2] + ssum[3])) +
              ((ssum[4] + ssum[5]) + (ssum[6] + ssum[7]));
    float inv = 1.0f / T;
    __half2 o0 = __floats2half2_rn(f0.x * inv, f0.y * inv);
    __half2 o1 = __floats2half2_rn(f1.x * inv, f1.y * inv);
    uint2 wout;
    wout.x = *(uint32_t*)&o0;
    wout.y = *(uint32_t*)&o1;
    ((uint2*)p)[tid] = wout;
}

// ---------------------------------------------------------------------------
// PV (fp16 mma): V read from packed QKV; output fp16.
// ---------------------------------------------------------------------------
__global__ __launch_bounds__(256)
void av_f16(const __half* __restrict__ P, const __half* __restrict__ QKV,
            __half* __restrict__ O) {
    __shared__ __align__(16) __half Ps[2][128][40];
    __shared__ __align__(16) __half Vs[2][32][88];

    int bh = blockIdx.y;
    int b = bh >> 4, h = bh & 15;
    int row0 = blockIdx.x * 128;
    const __half* pbase = P + (size_t)bh * SEQ * SEQ;
    const __half* vbase = QKV + (size_t)b * SEQ * QKVN + 2304 + h * HD;
    int tid = threadIdx.x;
    int lane = tid & 31;
    int warp = tid >> 5;
    int g4 = lane >> 2;
    int t4 = lane & 3;
    int p_row = tid >> 1;
    int p_k   = (tid & 1) * 16;

    float acc[10][4];
    #pragma unroll
    for (int nt = 0; nt < 10; nt++)
        #pragma unroll
        for (int r = 0; r < 4; r++) acc[nt][r] = 0.f;

    for (int i = tid; i < 128; i += 256) {
        int buf = i >> 6, r = (i & 63) >> 1, c = 72 + (i & 1) * 4;
        *(uint2*)&Vs[buf][r][c] = make_uint2(0u, 0u);
    }
    {
        const __half* ps = pbase + (size_t)(row0 + p_row) * SEQ + p_k;
        *(uint4*)&Ps[0][p_row][p_k]     = *(const uint4*)(ps);
        *(uint4*)&Ps[0][p_row][p_k + 8] = *(const uint4*)(ps + 8);
        for (int i = tid; i < 32 * 18; i += 256) {
            int r = i / 18, c = (i % 18) * 4;
            *(uint2*)&Vs[0][r][c] = *(const uint2*)(vbase + (size_t)r * QKVN + c);
        }
    }
    __syncthreads();

    for (int kt = 0; kt < SEQ / 32; kt++) {
        int cur = kt & 1;
        int nxt = cur ^ 1;
        uint4 pu0, pu1;
        uint2 vh[3]; int vr[3], vc[3]; int nv = 0;
        if (kt + 1 < SEQ / 32) {
            int k0 = (kt + 1) * 32;
            const __half* ps = pbase + (size_t)(row0 + p_row) * SEQ + k0 + p_k;
            pu0 = *(const uint4*)(ps);
            pu1 = *(const uint4*)(ps + 8);
            for (int i = tid; i < 32 * 18; i += 256) {
                int r = i / 18, c = (i % 18) * 4;
                vh[nv] = *(const uint2*)(vbase + (size_t)(k0 + r) * QKVN + c);
                vr[nv] = r; vc[nv] = c; nv++;
            }
        }
        #pragma unroll
        for (int kk = 0; kk < 32; kk += 16) {
            uint32_t a[4];
            int ar = warp * 16 + (lane & 15);
            int ac = kk + (lane >> 4) * 8;
            ldsm_x4(a, smem_u32(&Ps[cur][ar][ac]));
            #pragma unroll
            for (int np = 0; np < 5; np++) {
                int kr = kk + (lane & 7) + ((lane >> 3) & 1) * 8;
                int nc = np * 16 + (lane >> 4) * 8;
                uint32_t r[4];
                ldsm_x4_t(r, smem_u32(&Vs[cur][kr][nc]));
                mma_f16(acc[np * 2],     a, r[0], r[1]);
                mma_f16(acc[np * 2 + 1], a, r[2], r[3]);
            }
        }
        if (kt + 1 < SEQ / 32) {
            *(uint4*)&Ps[nxt][p_row][p_k]     = pu0;
            *(uint4*)&Ps[nxt][p_row][p_k + 8] = pu1;
            for (int i = 0; i < nv; i++)
                *(uint2*)&Vs[nxt][vr[i]][vc[i]] = vh[i];
        }
        __syncthreads();
    }

    #pragma unroll
    for (int nt = 0; nt < 9; nt++) {
        int col = h * HD + nt * 8 + t4 * 2;
        size_t r = (size_t)b * SEQ + row0 + warp * 16 + g4;
        *(__half2*)(O + r * D + col)       = __floats2half2_rn(acc[nt][0], acc[nt][1]);
        *(__half2*)(O + (r + 8) * D + col) = __floats2half2_rn(acc[nt][2], acc[nt][3]);
    }
}

// ---------------------------------------------------------------------------
// Launch
// ---------------------------------------------------------------------------
extern "C" void kernel_launch(void* const* d_in, const int* in_sizes, int n_in,
                              void* d_out, int out_size) {
    const float* hs    = (const float*)d_in[0];
    const float* ln1_w = (const float*)d_in[1];
    const float* ln1_b = (const float*)d_in[2];
    const float* q_w   = (const float*)d_in[3];
    const float* q_b   = (const float*)d_in[4];
    const float* k_w   = (const float*)d_in[5];
    const float* k_b   = (const float*)d_in[6];
    const float* v_w   = (const float*)d_in[7];
    const float* v_b   = (const float*)d_in[8];
    const float* o_w   = (const float*)d_in[9];
    const float* o_b   = (const float*)d_in[10];
    const float* ln2_w = (const float*)d_in[11];
    const float* ln2_b = (const float*)d_in[12];
    const float* fc1_w = (const float*)d_in[13];
    const float* fc1_b = (const float*)d_in[14];
    const float* fc2_w = (const float*)d_in[15];
    const float* fc2_b = (const float*)d_in[16];
    float* out = (float*)d_out;

    __half *xln, *qkv, *sc, *ao, *ff, *wqkv, *wo, *wfc1, *wfc2;
    float *h2, *bqkv;
    cudaGetSymbolAddress((void**)&xln,  g_xln);
    cudaGetSymbolAddress((void**)&qkv,  g_qkv);
    cudaGetSymbolAddress((void**)&sc,   g_scores);
    cudaGetSymbolAddress((void**)&ao,   g_ao);
    cudaGetSymbolAddress((void**)&h2,   g_h2);
    cudaGetSymbolAddress((void**)&ff,   g_ff);
    cudaGetSymbolAddress((void**)&wqkv, g_wqkv);
    cudaGetSymbolAddress((void**)&bqkv, g_bqkv);
    cudaGetSymbolAddress((void**)&wo,   g_wo);
    cudaGetSymbolAddress((void**)&wfc1, g_wfc1);
    cudaGetSymbolAddress((void**)&wfc2, g_wfc2);

    // 0. weight conversion / packing
    pack_qkv<<<(D * D / 4 + 255) / 256, 256>>>(q_w, k_w, v_w, q_b, k_b, v_b, wqkv, bqkv);
    conv_h<<<(D * D / 4 + 255) / 256, 256>>>(o_w, wo, D * D / 4);
    conv_h<<<(D * FFD / 4 + 255) / 256, 256>>>(fc1_w, wfc1, D * FFD / 4);
    conv_h<<<(FFD * D / 4 + 255) / 256, 256>>>(fc2_w, wfc2, FFD * D / 4);

    // 1. LN1 -> fp16
    ln_kernel<<<TOK, 288>>>(hs, ln1_w, ln1_b, xln);
    // 2. fused QKV projection (fp16 in/out)
    gemm_h<<<dim3(QKVN / 128, TOK / 128), 256>>>(xln, wqkv, bqkv, nullptr, qkv,
                                                 TOK, QKVN, D, D, 0, 1);
    // 3. scores
    scores_f16<<<dim3(SEQ / 128, SEQ / 128, NB * NH), 256>>>(qkv, sc);
    // 4. softmax
    softmax_h<<<NB * NH * SEQ, 256>>>(sc);
    // 5. attn @ V
    av_f16<<<dim3(SEQ / 128, NB * NH), 256>>>(sc, qkv, ao);
    // 6. O projection + residual1 (fp32 out)
    gemm_h<<<dim3(D / 128, TOK / 128), 256>>>(ao, wo, o_b, hs, h2,
                                              TOK, D, D, D, 0, 0);
    // 7. LN2 -> fp16
    ln_kernel<<<TOK, 288>>>(h2, ln2_w, ln2_b, xln);
    // 8. FC1 + GELU (fp16 out)
    gemm_h<<<dim3(FFD / 128, TOK / 128), 256>>>(xln, wfc1, fc1_b, nullptr, ff,
                                                TOK, FFD, D, D, 1, 1);
    // 9. FC2 + residual2 (fp32 out)
    gemm_h<<<dim3(D / 128, TOK / 128), 256>>>(ff, wfc2, fc2_b, h2, out,
                                              TOK, D, FFD, FFD, 0, 0);
}

// round 7
// speedup vs baseline: 6.4800x; 1.1779x over previous
#include <cuda_runtime.h>
#include <cuda_fp16.h>
#include <math.h>
#include <stdint.h>

// Problem dims
#define NB   8
#define SEQ  1024
#define TOK  (NB * SEQ)       // 8192
#define D    1152
#define FFD  4608
#define NH   16
#define HD   72
#define QKVN 3456             // 3*D

// ---------------------------------------------------------------------------
// Scratch (device globals)
// ---------------------------------------------------------------------------
__device__ __half g_xln[(size_t)TOK * D];
__device__ __half g_qkv[(size_t)TOK * QKVN];
__device__ __half g_ao[(size_t)TOK * D];
__device__ float  g_h2[(size_t)TOK * D];
__device__ __half g_ff[(size_t)TOK * FFD];
__device__ __half g_wqkv[(size_t)D * QKVN];
__device__ float  g_bqkv[QKVN];
__device__ __half g_wo[(size_t)D * D];
__device__ __half g_wfc1[(size_t)D * FFD];
__device__ __half g_wfc2[(size_t)FFD * D];

// ---------------------------------------------------------------------------
// helpers
// ---------------------------------------------------------------------------
__device__ __forceinline__ uint32_t smem_u32(const void* p) {
    return (uint32_t)__cvta_generic_to_shared(p);
}
__device__ __forceinline__ void ldsm_x4(uint32_t* r, uint32_t addr) {
    asm volatile("ldmatrix.sync.aligned.m8n8.x4.shared.b16 {%0,%1,%2,%3}, [%4];"
                 : "=r"(r[0]), "=r"(r[1]), "=r"(r[2]), "=r"(r[3]) : "r"(addr));
}
__device__ __forceinline__ void ldsm_x4_t(uint32_t* r, uint32_t addr) {
    asm volatile("ldmatrix.sync.aligned.m8n8.x4.trans.shared.b16 {%0,%1,%2,%3}, [%4];"
                 : "=r"(r[0]), "=r"(r[1]), "=r"(r[2]), "=r"(r[3]) : "r"(addr));
}
__device__ __forceinline__ void mma_f16(float* c, const uint32_t* a,
                                        uint32_t b0, uint32_t b1) {
    asm volatile(
        "mma.sync.aligned.m16n8k16.row.col.f32.f16.f16.f32 "
        "{%0,%1,%2,%3}, {%4,%5,%6,%7}, {%8,%9}, {%0,%1,%2,%3};\n"
        : "+f"(c[0]), "+f"(c[1]), "+f"(c[2]), "+f"(c[3])
        : "r"(a[0]), "r"(a[1]), "r"(a[2]), "r"(a[3]), "r"(b0), "r"(b1));
}
__device__ __forceinline__ uint2 f4_to_h4(float4 v) {
    __half2 lo = __floats2half2_rn(v.x, v.y);
    __half2 hi = __floats2half2_rn(v.z, v.w);
    uint2 r;
    r.x = *(uint32_t*)&lo;
    r.y = *(uint32_t*)&hi;
    return r;
}
__device__ __forceinline__ uint32_t packh2(float x, float y) {
    __half2 h = __floats2half2_rn(x, y);
    return *(uint32_t*)&h;
}
__device__ __forceinline__ void cp16(uint32_t dst, const void* src) {
    asm volatile("cp.async.cg.shared.global [%0], [%1], 16;" :: "r"(dst), "l"(src));
}
__device__ __forceinline__ void cp_commit() {
    asm volatile("cp.async.commit_group;");
}
__device__ __forceinline__ void cp_wait0() {
    asm volatile("cp.async.wait_group 0;");
}

// ---------------------------------------------------------------------------
// Weight conversion / packing
// ---------------------------------------------------------------------------
__global__ void pack_qkv(const float* __restrict__ qw, const float* __restrict__ kw,
                         const float* __restrict__ vw, const float* __restrict__ qb,
                         const float* __restrict__ kb, const float* __restrict__ vb,
                         __half* __restrict__ w16, float* __restrict__ b) {
    int idx = blockIdx.x * blockDim.x + threadIdx.x;
    int e = idx * 4;
    if (e < D * D) {
        int k = e / D, n = e % D;
        size_t o = (size_t)k * QKVN + n;
        *(uint2*)&w16[o]        = f4_to_h4(*(const float4*)(qw + e));
        *(uint2*)&w16[o + 1152] = f4_to_h4(*(const float4*)(kw + e));
        *(uint2*)&w16[o + 2304] = f4_to_h4(*(const float4*)(vw + e));
    }
    if (idx < D) {
        b[idx]        = qb[idx];
        b[idx + 1152] = kb[idx];
        b[idx + 2304] = vb[idx];
    }
}
__global__ void conv_h(const float* __restrict__ src, __half* __restrict__ dst, int n4) {
    int i = blockIdx.x * blockDim.x + threadIdx.x;
    if (i < n4)
        *(uint2*)&dst[(size_t)i * 4] = f4_to_h4(*(const float4*)(src + (size_t)i * 4));
}

// ---------------------------------------------------------------------------
// LayerNorm: fp32 in, fp16 out
// ---------------------------------------------------------------------------
__global__ void ln_kernel(const float* __restrict__ X, const float* __restrict__ gamma,
                          const float* __restrict__ beta, __half* __restrict__ Y) {
    int row = blockIdx.x;
    int tid = threadIdx.x;
    float4 v = ((const float4*)(X + (size_t)row * D))[tid];
    float s  = v.x + v.y + v.z + v.w;
    float sq = v.x * v.x + v.y * v.y + v.z * v.z + v.w * v.w;
    #pragma unroll
    for (int o = 16; o > 0; o >>= 1) {
        s  += __shfl_down_sync(0xffffffffu, s,  o);
        sq += __shfl_down_sync(0xffffffffu, sq, o);
    }
    __shared__ float ss[9], ssq[9];
    int w = tid >> 5, l = tid & 31;
    if (l == 0) { ss[w] = s; ssq[w] = sq; }
    __syncthreads();
    float ts = 0.f, tsq = 0.f;
    #pragma unroll
    for (int i = 0; i < 9; i++) { ts += ss[i]; tsq += ssq[i]; }
    const float invD = 1.0f / (float)D;
    float mean = ts * invD;
    float var  = tsq * invD - mean * mean;
    float rinv = rsqrtf(var + 1e-5f);
    float4 g = ((const float4*)gamma)[tid];
    float4 b = ((const float4*)beta)[tid];
    float4 o;
    o.x = (v.x - mean) * rinv * g.x + b.x;
    o.y = (v.y - mean) * rinv * g.y + b.y;
    o.z = (v.z - mean) * rinv * g.z + b.z;
    o.w = (v.w - mean) * rinv * g.w + b.w;
    *(uint2*)(Y + (size_t)row * D + tid * 4) = f4_to_h4(o);
}

// ---------------------------------------------------------------------------
// fp16 GEMM with cp.async staging
// ---------------------------------------------------------------------------
__global__ __launch_bounds__(256, 2)
void gemm_h(const __half* __restrict__ A, const __half* __restrict__ W,
            const float* __restrict__ bias, const float* __restrict__ res,
            void* __restrict__ Cv, int M, int N, int K, int lda,
            int gelu_act, int out_half)
{
    __shared__ __align__(16) __half As[2][128][40];
    __shared__ __align__(16) __half Bs[2][32][136];

    int tid  = threadIdx.x;
    int lane = tid & 31;
    int warp = tid >> 5;
    int mwbase = (warp & 1) * 64;
    int nwbase = (warp >> 1) * 32;
    int brow = blockIdx.y * 128;
    int bcol = blockIdx.x * 128;
    int g4 = lane >> 2;
    int t4 = lane & 3;

    int a_row = tid >> 1;
    int a_c   = (tid & 1) * 16;
    int b_row = tid >> 3;
    int b_c   = (tid & 7) * 16;

    const __half* Ap = A + (size_t)(brow + a_row) * lda + a_c;
    const __half* Wp = W + (size_t)b_row * N + bcol + b_c;

    float acc[4][4][4];
    #pragma unroll
    for (int mt = 0; mt < 4; mt++)
        #pragma unroll
        for (int nt = 0; nt < 4; nt++)
            #pragma unroll
            for (int r = 0; r < 4; r++) acc[mt][nt][r] = 0.f;

    cp16(smem_u32(&As[0][a_row][a_c]),     Ap);
    cp16(smem_u32(&As[0][a_row][a_c + 8]), Ap + 8);
    cp16(smem_u32(&Bs[0][b_row][b_c]),     Wp);
    cp16(smem_u32(&Bs[0][b_row][b_c + 8]), Wp + 8);
    cp_commit();
    cp_wait0();
    __syncthreads();

    int nk = K / 32;
    for (int kt = 0; kt < nk; kt++) {
        int cur = kt & 1;
        int nxt = cur ^ 1;
        if (kt + 1 < nk) {
            const __half* ap = Ap + (kt + 1) * 32;
            const __half* wp = Wp + (size_t)(kt + 1) * 32 * N;
            cp16(smem_u32(&As[nxt][a_row][a_c]),     ap);
            cp16(smem_u32(&As[nxt][a_row][a_c + 8]), ap + 8);
            cp16(smem_u32(&Bs[nxt][b_row][b_c]),     wp);
            cp16(smem_u32(&Bs[nxt][b_row][b_c + 8]), wp + 8);
            cp_commit();
        }
        #pragma unroll
        for (int kk = 0; kk < 32; kk += 16) {
            uint32_t bfr[4][2];
            #pragma unroll
            for (int np = 0; np < 2; np++) {
                int kr = kk + (lane & 7) + ((lane >> 3) & 1) * 8;
                int nc = nwbase + np * 16 + (lane >> 4) * 8;
                uint32_t r[4];
                ldsm_x4_t(r, smem_u32(&Bs[cur][kr][nc]));
                bfr[np * 2][0] = r[0]; bfr[np * 2][1] = r[1];
                bfr[np * 2 + 1][0] = r[2]; bfr[np * 2 + 1][1] = r[3];
            }
            #pragma unroll
            for (int mt = 0; mt < 4; mt++) {
                int ar = mwbase + mt * 16 + (lane & 15);
                int ac = kk + (lane >> 4) * 8;
                uint32_t a[4];
                ldsm_x4(a, smem_u32(&As[cur][ar][ac]));
                #pragma unroll
                for (int nt = 0; nt < 4; nt++)
                    mma_f16(acc[mt][nt], a, bfr[nt][0], bfr[nt][1]);
            }
        }
        if (kt + 1 < nk) cp_wait0();
        __syncthreads();
    }

    #pragma unroll
    for (int mt = 0; mt < 4; mt++) {
        #pragma unroll
        for (int nt = 0; nt < 4; nt++) {
            int col  = bcol + nwbase + nt * 8 + t4 * 2;
            float bx = bias[col], by = bias[col + 1];
            #pragma unroll
            for (int half = 0; half < 2; half++) {
                size_t row = (size_t)(brow + mwbase + mt * 16 + g4 + half * 8);
                float ox = acc[mt][nt][half * 2 + 0] + bx;
                float oy = acc[mt][nt][half * 2 + 1] + by;
                if (gelu_act) {
                    ox = 0.5f * ox * (1.0f + erff(ox * 0.70710678118f));
                    oy = 0.5f * oy * (1.0f + erff(oy * 0.70710678118f));
                }
                if (out_half) {
                    __half* Ch = (__half*)Cv;
                    *(__half2*)(Ch + row * N + col) = __floats2half2_rn(ox, oy);
                } else {
                    if (res) {
                        const float2 r = *(const float2*)(res + row * N + col);
                        ox += r.x; oy += r.y;
                    }
                    *(float2*)((float*)Cv + row * N + col) = make_float2(ox, oy);
                }
            }
        }
    }
}

// ---------------------------------------------------------------------------
// Flash attention (fused QK^T -> online softmax -> PV), fp16 mma, fp32 softmax.
// Grid: (SEQ/128, NB*NH). Block 256 (8 warps), warp owns 16 q-rows.
// Dynamic smem: Qs[128][88] + Ks[128][88] + Vs[128][88] = 67,584 B.
// ---------------------------------------------------------------------------
#define FAP 88   // smem pitch (halves)

__global__ __launch_bounds__(256, 1)
void flash_attn(const __half* __restrict__ QKV, __half* __restrict__ O) {
    extern __shared__ __half fsm[];
    __half (*Qs)[FAP] = (__half (*)[FAP])fsm;
    __half (*Ks)[FAP] = (__half (*)[FAP])(fsm + 128 * FAP);
    __half (*Vs)[FAP] = (__half (*)[FAP])(fsm + 2 * 128 * FAP);

    int bh = blockIdx.y;
    int b = bh >> 4, h = bh & 15;
    int row0 = blockIdx.x * 128;
    const __half* qbase = QKV + (size_t)b * SEQ * QKVN + h * HD;
    const __half* kbase = qbase + 1152;
    const __half* vbase = qbase + 2304;
    int tid = threadIdx.x;
    int lane = tid & 31;
    int warp = tid >> 5;
    int g4 = lane >> 2;
    int t4 = lane & 3;

    // stage Q (scale folded in), zero-pad d-cols 72..79 of Qs and Ks
    {
        const __half2 sc2 = __float2half2_rn(0.117851130198f);
        for (int i = tid; i < 128 * 18; i += 256) {
            int r = i / 18, c = (i % 18) * 4;
            uint2 u = *(const uint2*)(qbase + (size_t)(row0 + r) * QKVN + c);
            __half2 lo = __hmul2(*(__half2*)&u.x, sc2);
            __half2 hi = __hmul2(*(__half2*)&u.y, sc2);
            uint2 o;
            o.x = *(uint32_t*)&lo;
            o.y = *(uint32_t*)&hi;
            *(uint2*)&Qs[r][c] = o;
        }
        for (int i = tid; i < 128 * 2; i += 256) {
            int r = i >> 1, c = 72 + (i & 1) * 4;
            uint2 z = make_uint2(0u, 0u);
            *(uint2*)&Qs[r][c] = z;
            *(uint2*)&Ks[r][c] = z;
        }
    }
    __syncthreads();

    // preload Q fragments (5 k-chunks of 16 over padded d=80)
    uint32_t qf[5][4];
    #pragma unroll
    for (int kc = 0; kc < 5; kc++) {
        int ar = warp * 16 + (lane & 15);
        int ac = kc * 16 + (lane >> 4) * 8;
        ldsm_x4(qf[kc], smem_u32(&Qs[ar][ac]));
    }

    float m0 = -1e30f, m1 = -1e30f, l0 = 0.f, l1 = 0.f;
    float o[10][4];
    #pragma unroll
    for (int nt = 0; nt < 10; nt++)
        #pragma unroll
        for (int r = 0; r < 4; r++) o[nt][r] = 0.f;

    for (int jb = 0; jb < 8; jb++) {
        int j0 = jb * 128;
        // load K,V block (d-cols 0..71; pads stay zero for K)
        for (int i = tid; i < 128 * 18; i += 256) {
            int r = i / 18, c = (i % 18) * 4;
            *(uint2*)&Ks[r][c] = *(const uint2*)(kbase + (size_t)(j0 + r) * QKVN + c);
            *(uint2*)&Vs[r][c] = *(const uint2*)(vbase + (size_t)(j0 + r) * QKVN + c);
        }
        __syncthreads();

        // S = Q K^T  (warp computes 16x128)
        float s[16][4];
        #pragma unroll
        for (int nt = 0; nt < 16; nt++)
            #pragma unroll
            for (int r = 0; r < 4; r++) s[nt][r] = 0.f;
        #pragma unroll
        for (int np = 0; np < 8; np++) {
            int nr = np * 16 + (lane & 7) + (lane >> 4) * 8;
            #pragma unroll
            for (int kc = 0; kc < 5; kc++) {
                int nc = kc * 16 + ((lane >> 3) & 1) * 8;
                uint32_t r[4];
                ldsm_x4(r, smem_u32(&Ks[nr][nc]));
                mma_f16(s[np * 2],     qf[kc], r[0], r[1]);
                mma_f16(s[np * 2 + 1], qf[kc], r[2], r[3]);
            }
        }

        // online softmax (rows g4 and g4+8)
        float cm0 = -1e30f, cm1 = -1e30f;
        #pragma unroll
        for (int nt = 0; nt < 16; nt++) {
            cm0 = fmaxf(cm0, fmaxf(s[nt][0], s[nt][1]));
            cm1 = fmaxf(cm1, fmaxf(s[nt][2], s[nt][3]));
        }
        cm0 = fmaxf(cm0, __shfl_xor_sync(0xffffffffu, cm0, 1));
        cm0 = fmaxf(cm0, __shfl_xor_sync(0xffffffffu, cm0, 2));
        cm1 = fmaxf(cm1, __shfl_xor_sync(0xffffffffu, cm1, 1));
        cm1 = fmaxf(cm1, __shfl_xor_sync(0xffffffffu, cm1, 2));
        float nm0 = fmaxf(m0, cm0);
        float nm1 = fmaxf(m1, cm1);
        float f0 = __expf(m0 - nm0);
        float f1 = __expf(m1 - nm1);
        m0 = nm0; m1 = nm1;
        float sum0 = 0.f, sum1 = 0.f;
        #pragma unroll
        for (int nt = 0; nt < 16; nt++) {
            s[nt][0] = __expf(s[nt][0] - nm0);
            s[nt][1] = __expf(s[nt][1] - nm0);
            s[nt][2] = __expf(s[nt][2] - nm1);
            s[nt][3] = __expf(s[nt][3] - nm1);
            sum0 += s[nt][0] + s[nt][1];
            sum1 += s[nt][2] + s[nt][3];
        }
        l0 = l0 * f0 + sum0;        // lane-partial; reduced at end
        l1 = l1 * f1 + sum1;
        #pragma unroll
        for (int nt = 0; nt < 10; nt++) {
            o[nt][0] *= f0; o[nt][1] *= f0;
            o[nt][2] *= f1; o[nt][3] *= f1;
        }

        // O += P V  (P from registers: C-frag layout == A-frag layout)
        #pragma unroll
        for (int kc2 = 0; kc2 < 8; kc2++) {
            uint32_t a[4];
            a[0] = packh2(s[kc2 * 2][0],     s[kc2 * 2][1]);
            a[1] = packh2(s[kc2 * 2][2],     s[kc2 * 2][3]);
            a[2] = packh2(s[kc2 * 2 + 1][0], s[kc2 * 2 + 1][1]);
            a[3] = packh2(s[kc2 * 2 + 1][2], s[kc2 * 2 + 1][3]);
            int kr = kc2 * 16 + (lane & 7) + ((lane >> 3) & 1) * 8;
            #pragma unroll
            for (int np = 0; np < 5; np++) {
                int nc = np * 16 + (lane >> 4) * 8;
                uint32_t r[4];
                ldsm_x4_t(r, smem_u32(&Vs[kr][nc]));
                mma_f16(o[np * 2],     a, r[0], r[1]);
                mma_f16(o[np * 2 + 1], a, r[2], r[3]);
            }
        }
        __syncthreads();
    }

    // finalize: reduce l across t4 group, normalize, write 72 cols
    l0 += __shfl_xor_sync(0xffffffffu, l0, 1);
    l0 += __shfl_xor_sync(0xffffffffu, l0, 2);
    l1 += __shfl_xor_sync(0xffffffffu, l1, 1);
    l1 += __shfl_xor_sync(0xffffffffu, l1, 2);
    float inv0 = 1.0f / l0;
    float inv1 = 1.0f / l1;
    #pragma unroll
    for (int nt = 0; nt < 9; nt++) {
        int col = h * HD + nt * 8 + t4 * 2;
        size_t r = (size_t)b * SEQ + row0 + warp * 16 + g4;
        *(__half2*)(O + r * D + col)       = __floats2half2_rn(o[nt][0] * inv0, o[nt][1] * inv0);
        *(__half2*)(O + (r + 8) * D + col) = __floats2half2_rn(o[nt][2] * inv1, o[nt][3] * inv1);
    }
}

// ---------------------------------------------------------------------------
// Launch
// ---------------------------------------------------------------------------
extern "C" void kernel_launch(void* const* d_in, const int* in_sizes, int n_in,
                              void* d_out, int out_size) {
    const float* hs    = (const float*)d_in[0];
    const float* ln1_w = (const float*)d_in[1];
    const float* ln1_b = (const float*)d_in[2];
    const float* q_w   = (const float*)d_in[3];
    const float* q_b   = (const float*)d_in[4];
    const float* k_w   = (const float*)d_in[5];
    const float* k_b   = (const float*)d_in[6];
    const float* v_w   = (const float*)d_in[7];
    const float* v_b   = (const float*)d_in[8];
    const float* o_w   = (const float*)d_in[9];
    const float* o_b   = (const float*)d_in[10];
    const float* ln2_w = (const float*)d_in[11];
    const float* ln2_b = (const float*)d_in[12];
    const float* fc1_w = (const float*)d_in[13];
    const float* fc1_b = (const float*)d_in[14];
    const float* fc2_w = (const float*)d_in[15];
    const float* fc2_b = (const float*)d_in[16];
    float* out = (float*)d_out;

    __half *xln, *qkv, *ao, *ff, *wqkv, *wo, *wfc1, *wfc2;
    float *h2, *bqkv;
    cudaGetSymbolAddress((void**)&xln,  g_xln);
    cudaGetSymbolAddress((void**)&qkv,  g_qkv);
    cudaGetSymbolAddress((void**)&ao,   g_ao);
    cudaGetSymbolAddress((void**)&h2,   g_h2);
    cudaGetSymbolAddress((void**)&ff,   g_ff);
    cudaGetSymbolAddress((void**)&wqkv, g_wqkv);
    cudaGetSymbolAddress((void**)&bqkv, g_bqkv);
    cudaGetSymbolAddress((void**)&wo,   g_wo);
    cudaGetSymbolAddress((void**)&wfc1, g_wfc1);
    cudaGetSymbolAddress((void**)&wfc2, g_wfc2);

    const int FA_SMEM = 3 * 128 * FAP * (int)sizeof(__half);   // 67,584 B
    cudaFuncSetAttribute(flash_attn, cudaFuncAttributeMaxDynamicSharedMemorySize,
                         FA_SMEM);

    // 0. weight conversion / packing
    pack_qkv<<<(D * D / 4 + 255) / 256, 256>>>(q_w, k_w, v_w, q_b, k_b, v_b, wqkv, bqkv);
    conv_h<<<(D * D / 4 + 255) / 256, 256>>>(o_w, wo, D * D / 4);
    conv_h<<<(D * FFD / 4 + 255) / 256, 256>>>(fc1_w, wfc1, D * FFD / 4);
    conv_h<<<(FFD * D / 4 + 255) / 256, 256>>>(fc2_w, wfc2, FFD * D / 4);

    // 1. LN1 -> fp16
    ln_kernel<<<TOK, 288>>>(hs, ln1_w, ln1_b, xln);
    // 2. fused QKV projection
    gemm_h<<<dim3(QKVN / 128, TOK / 128), 256>>>(xln, wqkv, bqkv, nullptr, qkv,
                                                 TOK, QKVN, D, D, 0, 1);
    // 3-5. fused attention
    flash_attn<<<dim3(SEQ / 128, NB * NH), 256, FA_SMEM>>>(qkv, ao);
    // 6. O projection + residual1 (fp32 out)
    gemm_h<<<dim3(D / 128, TOK / 128), 256>>>(ao, wo, o_b, hs, h2,
                                              TOK, D, D, D, 0, 0);
    // 7. LN2 -> fp16
    ln_kernel<<<TOK, 288>>>(h2, ln2_w, ln2_b, xln);
    // 8. FC1 + GELU (fp16 out)
    gemm_h<<<dim3(FFD / 128, TOK / 128), 256>>>(xln, wfc1, fc1_b, nullptr, ff,
                                                TOK, FFD, D, D, 1, 1);
    // 9. FC2 + residual2 (fp32 out)
    gemm_h<<<dim3(D / 128, TOK / 128), 256>>>(ff, wfc2, fc2_b, h2, out,
                                              TOK, D, FFD, FFD, 0, 0);
}

// round 8
// speedup vs baseline: 7.0416x; 1.0867x over previous
#include <cuda_runtime.h>
#include <cuda_fp16.h>
#include <math.h>
#include <stdint.h>

// Problem dims
#define NB   8
#define SEQ  1024
#define TOK  (NB * SEQ)       // 8192
#define D    1152
#define FFD  4608
#define NH   16
#define HD   72
#define QKVN 3456             // 3*D

// ---------------------------------------------------------------------------
// Scratch (device globals)
// ---------------------------------------------------------------------------
__device__ __half g_xln[(size_t)TOK * D];
__device__ __half g_qkv[(size_t)TOK * QKVN];
__device__ __half g_ao[(size_t)TOK * D];
__device__ float  g_h2[(size_t)TOK * D];
__device__ __half g_ff[(size_t)TOK * FFD];
__device__ __half g_wqkv[(size_t)D * QKVN];
__device__ float  g_bqkv[QKVN];
__device__ __half g_wo[(size_t)D * D];
__device__ __half g_wfc1[(size_t)D * FFD];
__device__ __half g_wfc2[(size_t)FFD * D];

// ---------------------------------------------------------------------------
// helpers
// ---------------------------------------------------------------------------
__device__ __forceinline__ uint32_t smem_u32(const void* p) {
    return (uint32_t)__cvta_generic_to_shared(p);
}
__device__ __forceinline__ void ldsm_x4(uint32_t* r, uint32_t addr) {
    asm volatile("ldmatrix.sync.aligned.m8n8.x4.shared.b16 {%0,%1,%2,%3}, [%4];"
                 : "=r"(r[0]), "=r"(r[1]), "=r"(r[2]), "=r"(r[3]) : "r"(addr));
}
__device__ __forceinline__ void ldsm_x4_t(uint32_t* r, uint32_t addr) {
    asm volatile("ldmatrix.sync.aligned.m8n8.x4.trans.shared.b16 {%0,%1,%2,%3}, [%4];"
                 : "=r"(r[0]), "=r"(r[1]), "=r"(r[2]), "=r"(r[3]) : "r"(addr));
}
__device__ __forceinline__ void mma_f16(float* c, const uint32_t* a,
                                        uint32_t b0, uint32_t b1) {
    asm volatile(
        "mma.sync.aligned.m16n8k16.row.col.f32.f16.f16.f32 "
        "{%0,%1,%2,%3}, {%4,%5,%6,%7}, {%8,%9}, {%0,%1,%2,%3};\n"
        : "+f"(c[0]), "+f"(c[1]), "+f"(c[2]), "+f"(c[3])
        : "r"(a[0]), "r"(a[1]), "r"(a[2]), "r"(a[3]), "r"(b0), "r"(b1));
}
__device__ __forceinline__ uint2 f4_to_h4(float4 v) {
    __half2 lo = __floats2half2_rn(v.x, v.y);
    __half2 hi = __floats2half2_rn(v.z, v.w);
    uint2 r;
    r.x = *(uint32_t*)&lo;
    r.y = *(uint32_t*)&hi;
    return r;
}
__device__ __forceinline__ uint32_t packh2(float x, float y) {
    __half2 h = __floats2half2_rn(x, y);
    return *(uint32_t*)&h;
}
__device__ __forceinline__ void cp16(uint32_t dst, const void* src) {
    asm volatile("cp.async.cg.shared.global [%0], [%1], 16;" :: "r"(dst), "l"(src));
}
__device__ __forceinline__ void cp_commit() {
    asm volatile("cp.async.commit_group;");
}

// ---------------------------------------------------------------------------
// Weight conversion / packing
// ---------------------------------------------------------------------------
__global__ void pack_qkv(const float* __restrict__ qw, const float* __restrict__ kw,
                         const float* __restrict__ vw, const float* __restrict__ qb,
                         const float* __restrict__ kb, const float* __restrict__ vb,
                         __half* __restrict__ w16, float* __restrict__ b) {
    int idx = blockIdx.x * blockDim.x + threadIdx.x;
    int e = idx * 4;
    if (e < D * D) {
        int k = e / D, n = e % D;
        size_t o = (size_t)k * QKVN + n;
        *(uint2*)&w16[o]        = f4_to_h4(*(const float4*)(qw + e));
        *(uint2*)&w16[o + 1152] = f4_to_h4(*(const float4*)(kw + e));
        *(uint2*)&w16[o + 2304] = f4_to_h4(*(const float4*)(vw + e));
    }
    if (idx < D) {
        b[idx]        = qb[idx];
        b[idx + 1152] = kb[idx];
        b[idx + 2304] = vb[idx];
    }
}
__global__ void conv_h(const float* __restrict__ src, __half* __restrict__ dst, int n4) {
    int i = blockIdx.x * blockDim.x + threadIdx.x;
    if (i < n4)
        *(uint2*)&dst[(size_t)i * 4] = f4_to_h4(*(const float4*)(src + (size_t)i * 4));
}

// ---------------------------------------------------------------------------
// LayerNorm: fp32 in, fp16 out
// ---------------------------------------------------------------------------
__global__ void ln_kernel(const float* __restrict__ X, const float* __restrict__ gamma,
                          const float* __restrict__ beta, __half* __restrict__ Y) {
    int row = blockIdx.x;
    int tid = threadIdx.x;
    float4 v = ((const float4*)(X + (size_t)row * D))[tid];
    float s  = v.x + v.y + v.z + v.w;
    float sq = v.x * v.x + v.y * v.y + v.z * v.z + v.w * v.w;
    #pragma unroll
    for (int o = 16; o > 0; o >>= 1) {
        s  += __shfl_down_sync(0xffffffffu, s,  o);
        sq += __shfl_down_sync(0xffffffffu, sq, o);
    }
    __shared__ float ss[9], ssq[9];
    int w = tid >> 5, l = tid & 31;
    if (l == 0) { ss[w] = s; ssq[w] = sq; }
    __syncthreads();
    float ts = 0.f, tsq = 0.f;
    #pragma unroll
    for (int i = 0; i < 9; i++) { ts += ss[i]; tsq += ssq[i]; }
    const float invD = 1.0f / (float)D;
    float mean = ts * invD;
    float var  = tsq * invD - mean * mean;
    float rinv = rsqrtf(var + 1e-5f);
    float4 g = ((const float4*)gamma)[tid];
    float4 b = ((const float4*)beta)[tid];
    float4 o;
    o.x = (v.x - mean) * rinv * g.x + b.x;
    o.y = (v.y - mean) * rinv * g.y + b.y;
    o.z = (v.z - mean) * rinv * g.z + b.z;
    o.w = (v.w - mean) * rinv * g.w + b.w;
    *(uint2*)(Y + (size_t)row * D + tid * 4) = f4_to_h4(o);
}

// ---------------------------------------------------------------------------
// fp16 GEMM, 4-stage cp.async pipeline.
// C[M,N] = A[M,K](fp16, row stride lda) @ W[K,N](fp16) + bias (+GELU) (+res)
// 128x128x32 tile, 8 warps (2x4), warp tile 64x32.
// Dynamic smem: 4 * (128*40 + 32*136) halves = 75,776 B.
// ---------------------------------------------------------------------------
#define GSTG 4
#define AP_  40
#define BP_  136
#define A_ST (128 * AP_)          // halves per A stage
#define B_ST (32 * BP_)           // halves per B stage
#define GEMM_SMEM ((GSTG * (A_ST + B_ST)) * 2)

__global__ __launch_bounds__(256, 2)
void gemm_h(const __half* __restrict__ A, const __half* __restrict__ W,
            const float* __restrict__ bias, const float* __restrict__ res,
            void* __restrict__ Cv, int M, int N, int K, int lda,
            int gelu_act, int out_half)
{
    extern __shared__ __half dsm[];
    __half* Asm = dsm;                    // [GSTG][128][AP_]
    __half* Bsm = dsm + GSTG * A_ST;      // [GSTG][32][BP_]

    int tid  = threadIdx.x;
    int lane = tid & 31;
    int warp = tid >> 5;
    int mwbase = (warp & 1) * 64;
    int nwbase = (warp >> 1) * 32;
    int brow = blockIdx.y * 128;
    int bcol = blockIdx.x * 128;
    int g4 = lane >> 2;
    int t4 = lane & 3;

    int a_row = tid >> 1;
    int a_c   = (tid & 1) * 16;
    int b_row = tid >> 3;
    int b_c   = (tid & 7) * 16;

    const __half* Ap = A + (size_t)(brow + a_row) * lda + a_c;
    const __half* Wp = W + (size_t)b_row * N + bcol + b_c;

    uint32_t as_base = smem_u32(Asm) + (a_row * AP_ + a_c) * 2;
    uint32_t bs_base = smem_u32(Bsm) + (b_row * BP_ + b_c) * 2;

    float acc[4][4][4];
    #pragma unroll
    for (int mt = 0; mt < 4; mt++)
        #pragma unroll
        for (int nt = 0; nt < 4; nt++)
            #pragma unroll
            for (int r = 0; r < 4; r++) acc[mt][nt][r] = 0.f;

    int nk = K / 32;
    // prologue: stages 0..GSTG-2
    #pragma unroll
    for (int s = 0; s < GSTG - 1; s++) {
        const __half* ap = Ap + s * 32;
        const __half* wp = Wp + (size_t)s * 32 * N;
        uint32_t ad = as_base + s * A_ST * 2;
        uint32_t bd = bs_base + s * B_ST * 2;
        cp16(ad,      ap);
        cp16(ad + 16, ap + 8);
        cp16(bd,      wp);
        cp16(bd + 16, wp + 8);
        cp_commit();
    }

    for (int kt = 0; kt < nk; kt++) {
        int cur = kt & (GSTG - 1);
        asm volatile("cp.async.wait_group %0;" :: "n"(GSTG - 2));
        __syncthreads();
        // issue load for tile kt+GSTG-1 (into the buffer freed last iteration)
        if (kt + GSTG - 1 < nk) {
            int nst = (kt + GSTG - 1) & (GSTG - 1);
            const __half* ap = Ap + (kt + GSTG - 1) * 32;
            const __half* wp = Wp + (size_t)(kt + GSTG - 1) * 32 * N;
            uint32_t ad = as_base + nst * A_ST * 2;
            uint32_t bd = bs_base + nst * B_ST * 2;
            cp16(ad,      ap);
            cp16(ad + 16, ap + 8);
            cp16(bd,      wp);
            cp16(bd + 16, wp + 8);
        }
        cp_commit();   // commit every iteration to keep group accounting uniform
        // math on stage cur
        const __half* Abuf = Asm + cur * A_ST;
        const __half* Bbuf = Bsm + cur * B_ST;
        #pragma unroll
        for (int kk = 0; kk < 32; kk += 16) {
            uint32_t bfr[4][2];
            #pragma unroll
            for (int np = 0; np < 2; np++) {
                int kr = kk + (lane & 7) + ((lane >> 3) & 1) * 8;
                int nc = nwbase + np * 16 + (lane >> 4) * 8;
                uint32_t r[4];
                ldsm_x4_t(r, smem_u32(Bbuf + kr * BP_ + nc));
                bfr[np * 2][0] = r[0]; bfr[np * 2][1] = r[1];
                bfr[np * 2 + 1][0] = r[2]; bfr[np * 2 + 1][1] = r[3];
            }
            #pragma unroll
            for (int mt = 0; mt < 4; mt++) {
                int ar = mwbase + mt * 16 + (lane & 15);
                int ac = kk + (lane >> 4) * 8;
                uint32_t a[4];
                ldsm_x4(a, smem_u32(Abuf + ar * AP_ + ac));
                #pragma unroll
                for (int nt = 0; nt < 4; nt++)
                    mma_f16(acc[mt][nt], a, bfr[nt][0], bfr[nt][1]);
            }
        }
    }

    __syncthreads();
    #pragma unroll
    for (int mt = 0; mt < 4; mt++) {
        #pragma unroll
        for (int nt = 0; nt < 4; nt++) {
            int col  = bcol + nwbase + nt * 8 + t4 * 2;
            float bx = bias[col], by = bias[col + 1];
            #pragma unroll
            for (int half = 0; half < 2; half++) {
                size_t row = (size_t)(brow + mwbase + mt * 16 + g4 + half * 8);
                float ox = acc[mt][nt][half * 2 + 0] + bx;
                float oy = acc[mt][nt][half * 2 + 1] + by;
                if (gelu_act) {
                    ox = 0.5f * ox * (1.0f + erff(ox * 0.70710678118f));
                    oy = 0.5f * oy * (1.0f + erff(oy * 0.70710678118f));
                }
                if (out_half) {
                    __half* Ch = (__half*)Cv;
                    *(__half2*)(Ch + row * N + col) = __floats2half2_rn(ox, oy);
                } else {
                    if (res) {
                        const float2 r = *(const float2*)(res + row * N + col);
                        ox += r.x; oy += r.y;
                    }
                    *(float2*)((float*)Cv + row * N + col) = make_float2(ox, oy);
                }
            }
        }
    }
}

// ---------------------------------------------------------------------------
// Flash attention (unchanged from R7)
// ---------------------------------------------------------------------------
#define FAP 88

__global__ __launch_bounds__(256, 1)
void flash_attn(const __half* __restrict__ QKV, __half* __restrict__ O) {
    extern __shared__ __half fsm[];
    __half (*Qs)[FAP] = (__half (*)[FAP])fsm;
    __half (*Ks)[FAP] = (__half (*)[FAP])(fsm + 128 * FAP);
    __half (*Vs)[FAP] = (__half (*)[FAP])(fsm + 2 * 128 * FAP);

    int bh = blockIdx.y;
    int b = bh >> 4, h = bh & 15;
    int row0 = blockIdx.x * 128;
    const __half* qbase = QKV + (size_t)b * SEQ * QKVN + h * HD;
    const __half* kbase = qbase + 1152;
    const __half* vbase = qbase + 2304;
    int tid = threadIdx.x;
    int lane = tid & 31;
    int warp = tid >> 5;
    int g4 = lane >> 2;
    int t4 = lane & 3;

    {
        const __half2 sc2 = __float2half2_rn(0.117851130198f);
        for (int i = tid; i < 128 * 18; i += 256) {
            int r = i / 18, c = (i % 18) * 4;
            uint2 u = *(const uint2*)(qbase + (size_t)(row0 + r) * QKVN + c);
            __half2 lo = __hmul2(*(__half2*)&u.x, sc2);
            __half2 hi = __hmul2(*(__half2*)&u.y, sc2);
            uint2 o;
            o.x = *(uint32_t*)&lo;
            o.y = *(uint32_t*)&hi;
            *(uint2*)&Qs[r][c] = o;
        }
        for (int i = tid; i < 128 * 2; i += 256) {
            int r = i >> 1, c = 72 + (i & 1) * 4;
            uint2 z = make_uint2(0u, 0u);
            *(uint2*)&Qs[r][c] = z;
            *(uint2*)&Ks[r][c] = z;
        }
    }
    __syncthreads();

    uint32_t qf[5][4];
    #pragma unroll
    for (int kc = 0; kc < 5; kc++) {
        int ar = warp * 16 + (lane & 15);
        int ac = kc * 16 + (lane >> 4) * 8;
        ldsm_x4(qf[kc], smem_u32(&Qs[ar][ac]));
    }

    float m0 = -1e30f, m1 = -1e30f, l0 = 0.f, l1 = 0.f;
    float o[10][4];
    #pragma unroll
    for (int nt = 0; nt < 10; nt++)
        #pragma unroll
        for (int r = 0; r < 4; r++) o[nt][r] = 0.f;

    for (int jb = 0; jb < 8; jb++) {
        int j0 = jb * 128;
        for (int i = tid; i < 128 * 18; i += 256) {
            int r = i / 18, c = (i % 18) * 4;
            *(uint2*)&Ks[r][c] = *(const uint2*)(kbase + (size_t)(j0 + r) * QKVN + c);
            *(uint2*)&Vs[r][c] = *(const uint2*)(vbase + (size_t)(j0 + r) * QKVN + c);
        }
        __syncthreads();

        float s[16][4];
        #pragma unroll
        for (int nt = 0; nt < 16; nt++)
            #pragma unroll
            for (int r = 0; r < 4; r++) s[nt][r] = 0.f;
        #pragma unroll
        for (int np = 0; np < 8; np++) {
            int nr = np * 16 + (lane & 7) + (lane >> 4) * 8;
            #pragma unroll
            for (int kc = 0; kc < 5; kc++) {
                int nc = kc * 16 + ((lane >> 3) & 1) * 8;
                uint32_t r[4];
                ldsm_x4(r, smem_u32(&Ks[nr][nc]));
                mma_f16(s[np * 2],     qf[kc], r[0], r[1]);
                mma_f16(s[np * 2 + 1], qf[kc], r[2], r[3]);
            }
        }

        float cm0 = -1e30f, cm1 = -1e30f;
        #pragma unroll
        for (int nt = 0; nt < 16; nt++) {
            cm0 = fmaxf(cm0, fmaxf(s[nt][0], s[nt][1]));
            cm1 = fmaxf(cm1, fmaxf(s[nt][2], s[nt][3]));
        }
        cm0 = fmaxf(cm0, __shfl_xor_sync(0xffffffffu, cm0, 1));
        cm0 = fmaxf(cm0, __shfl_xor_sync(0xffffffffu, cm0, 2));
        cm1 = fmaxf(cm1, __shfl_xor_sync(0xffffffffu, cm1, 1));
        cm1 = fmaxf(cm1, __shfl_xor_sync(0xffffffffu, cm1, 2));
        float nm0 = fmaxf(m0, cm0);
        float nm1 = fmaxf(m1, cm1);
        float f0 = __expf(m0 - nm0);
        float f1 = __expf(m1 - nm1);
        m0 = nm0; m1 = nm1;
        float sum0 = 0.f, sum1 = 0.f;
        #pragma unroll
        for (int nt = 0; nt < 16; nt++) {
            s[nt][0] = __expf(s[nt][0] - nm0);
            s[nt][1] = __expf(s[nt][1] - nm0);
            s[nt][2] = __expf(s[nt][2] - nm1);
            s[nt][3] = __expf(s[nt][3] - nm1);
            sum0 += s[nt][0] + s[nt][1];
            sum1 += s[nt][2] + s[nt][3];
        }
        l0 = l0 * f0 + sum0;
        l1 = l1 * f1 + sum1;
        #pragma unroll
        for (int nt = 0; nt < 10; nt++) {
            o[nt][0] *= f0; o[nt][1] *= f0;
            o[nt][2] *= f1; o[nt][3] *= f1;
        }

        #pragma unroll
        for (int kc2 = 0; kc2 < 8; kc2++) {
            uint32_t a[4];
            a[0] = packh2(s[kc2 * 2][0],     s[kc2 * 2][1]);
            a[1] = packh2(s[kc2 * 2][2],     s[kc2 * 2][3]);
            a[2] = packh2(s[kc2 * 2 + 1][0], s[kc2 * 2 + 1][1]);
            a[3] = packh2(s[kc2 * 2 + 1][2], s[kc2 * 2 + 1][3]);
            int kr = kc2 * 16 + (lane & 7) + ((lane >> 3) & 1) * 8;
            #pragma unroll
            for (int np = 0; np < 5; np++) {
                int nc = np * 16 + (lane >> 4) * 8;
                uint32_t r[4];
                ldsm_x4_t(r, smem_u32(&Vs[kr][nc]));
                mma_f16(o[np * 2],     a, r[0], r[1]);
                mma_f16(o[np * 2 + 1], a, r[2], r[3]);
            }
        }
        __syncthreads();
    }

    l0 += __shfl_xor_sync(0xffffffffu, l0, 1);
    l0 += __shfl_xor_sync(0xffffffffu, l0, 2);
    l1 += __shfl_xor_sync(0xffffffffu, l1, 1);
    l1 += __shfl_xor_sync(0xffffffffu, l1, 2);
    float inv0 = 1.0f / l0;
    float inv1 = 1.0f / l1;
    #pragma unroll
    for (int nt = 0; nt < 9; nt++) {
        int col = h * HD + nt * 8 + t4 * 2;
        size_t r = (size_t)b * SEQ + row0 + warp * 16 + g4;
        *(__half2*)(O + r * D + col)       = __floats2half2_rn(o[nt][0] * inv0, o[nt][1] * inv0);
        *(__half2*)(O + (r + 8) * D + col) = __floats2half2_rn(o[nt][2] * inv1, o[nt][3] * inv1);
    }
}

// ---------------------------------------------------------------------------
// Launch
// ---------------------------------------------------------------------------
extern "C" void kernel_launch(void* const* d_in, const int* in_sizes, int n_in,
                              void* d_out, int out_size) {
    const float* hs    = (const float*)d_in[0];
    const float* ln1_w = (const float*)d_in[1];
    const float* ln1_b = (const float*)d_in[2];
    const float* q_w   = (const float*)d_in[3];
    const float* q_b   = (const float*)d_in[4];
    const float* k_w   = (const float*)d_in[5];
    const float* k_b   = (const float*)d_in[6];
    const float* v_w   = (const float*)d_in[7];
    const float* v_b   = (const float*)d_in[8];
    const float* o_w   = (const float*)d_in[9];
    const float* o_b   = (const float*)d_in[10];
    const float* ln2_w = (const float*)d_in[11];
    const float* ln2_b = (const float*)d_in[12];
    const float* fc1_w = (const float*)d_in[13];
    const float* fc1_b = (const float*)d_in[14];
    const float* fc2_w = (const float*)d_in[15];
    const float* fc2_b = (const float*)d_in[16];
    float* out = (float*)d_out;

    __half *xln, *qkv, *ao, *ff, *wqkv, *wo, *wfc1, *wfc2;
    float *h2, *bqkv;
    cudaGetSymbolAddress((void**)&xln,  g_xln);
    cudaGetSymbolAddress((void**)&qkv,  g_qkv);
    cudaGetSymbolAddress((void**)&ao,   g_ao);
    cudaGetSymbolAddress((void**)&h2,   g_h2);
    cudaGetSymbolAddress((void**)&ff,   g_ff);
    cudaGetSymbolAddress((void**)&wqkv, g_wqkv);
    cudaGetSymbolAddress((void**)&bqkv, g_bqkv);
    cudaGetSymbolAddress((void**)&wo,   g_wo);
    cudaGetSymbolAddress((void**)&wfc1, g_wfc1);
    cudaGetSymbolAddress((void**)&wfc2, g_wfc2);

    const int FA_SMEM = 3 * 128 * FAP * (int)sizeof(__half);   // 67,584 B
    cudaFuncSetAttribute(flash_attn, cudaFuncAttributeMaxDynamicSharedMemorySize,
                         FA_SMEM);
    cudaFuncSetAttribute(gemm_h, cudaFuncAttributeMaxDynamicSharedMemorySize,
                         GEMM_SMEM);                            // 75,776 B

    // 0. weight conversion / packing
    pack_qkv<<<(D * D / 4 + 255) / 256, 256>>>(q_w, k_w, v_w, q_b, k_b, v_b, wqkv, bqkv);
    conv_h<<<(D * D / 4 + 255) / 256, 256>>>(o_w, wo, D * D / 4);
    conv_h<<<(D * FFD / 4 + 255) / 256, 256>>>(fc1_w, wfc1, D * FFD / 4);
    conv_h<<<(FFD * D / 4 + 255) / 256, 256>>>(fc2_w, wfc2, FFD * D / 4);

    // 1. LN1 -> fp16
    ln_kernel<<<TOK, 288>>>(hs, ln1_w, ln1_b, xln);
    // 2. fused QKV projection
    gemm_h<<<dim3(QKVN / 128, TOK / 128), 256, GEMM_SMEM>>>(xln, wqkv, bqkv, nullptr, qkv,
                                                            TOK, QKVN, D, D, 0, 1);
    // 3-5. fused attention
    flash_attn<<<dim3(SEQ / 128, NB * NH), 256, FA_SMEM>>>(qkv, ao);
    // 6. O projection + residual1 (fp32 out)
    gemm_h<<<dim3(D / 128, TOK / 128), 256, GEMM_SMEM>>>(ao, wo, o_b, hs, h2,
                                                         TOK, D, D, D, 0, 0);
    // 7. LN2 -> fp16
    ln_kernel<<<TOK, 288>>>(h2, ln2_w, ln2_b, xln);
    // 8. FC1 + GELU (fp16 out)
    gemm_h<<<dim3(FFD / 128, TOK / 128), 256, GEMM_SMEM>>>(xln, wfc1, fc1_b, nullptr, ff,
                                                           TOK, FFD, D, D, 1, 1);
    // 9. FC2 + residual2 (fp32 out)
    gemm_h<<<dim3(D / 128, TOK / 128), 256, GEMM_SMEM>>>(ff, wfc2, fc2_b, h2, out,
                                                         TOK, D, FFD, FFD, 0, 0);
}

// round 12
// speedup vs baseline: 7.3905x; 1.0496x over previous
#include <cuda_runtime.h>
#include <cuda_fp16.h>
#include <math.h>
#include <stdint.h>

// Problem dims
#define NB   8
#define SEQ  1024
#define TOK  (NB * SEQ)       // 8192
#define D    1152
#define FFD  4608
#define NH   16
#define HD   72
#define QKVN 3456             // 3*D

// ---------------------------------------------------------------------------
// Scratch (device globals)
// ---------------------------------------------------------------------------
__device__ __half g_xln[(size_t)TOK * D];
__device__ __half g_qkv[(size_t)TOK * QKVN];
__device__ __half g_ao[(size_t)TOK * D];
__device__ float  g_h2[(size_t)TOK * D];
__device__ __half g_ff[(size_t)TOK * FFD];
__device__ __half g_wqkv[(size_t)D * QKVN];
__device__ float  g_bqkv[QKVN];
__device__ __half g_wo[(size_t)D * D];
__device__ __half g_wfc1[(size_t)D * FFD];
__device__ __half g_wfc2[(size_t)FFD * D];

// ---------------------------------------------------------------------------
// helpers
// ---------------------------------------------------------------------------
__device__ __forceinline__ uint32_t smem_u32(const void* p) {
    return (uint32_t)__cvta_generic_to_shared(p);
}
__device__ __forceinline__ void ldsm_x4(uint32_t* r, uint32_t addr) {
    asm volatile("ldmatrix.sync.aligned.m8n8.x4.shared.b16 {%0,%1,%2,%3}, [%4];"
                 : "=r"(r[0]), "=r"(r[1]), "=r"(r[2]), "=r"(r[3]) : "r"(addr));
}
__device__ __forceinline__ void ldsm_x4_t(uint32_t* r, uint32_t addr) {
    asm volatile("ldmatrix.sync.aligned.m8n8.x4.trans.shared.b16 {%0,%1,%2,%3}, [%4];"
                 : "=r"(r[0]), "=r"(r[1]), "=r"(r[2]), "=r"(r[3]) : "r"(addr));
}
__device__ __forceinline__ void mma_f16(float* c, const uint32_t* a,
                                        uint32_t b0, uint32_t b1) {
    asm volatile(
        "mma.sync.aligned.m16n8k16.row.col.f32.f16.f16.f32 "
        "{%0,%1,%2,%3}, {%4,%5,%6,%7}, {%8,%9}, {%0,%1,%2,%3};\n"
        : "+f"(c[0]), "+f"(c[1]), "+f"(c[2]), "+f"(c[3])
        : "r"(a[0]), "r"(a[1]), "r"(a[2]), "r"(a[3]), "r"(b0), "r"(b1));
}
__device__ __forceinline__ uint2 f4_to_h4(float4 v) {
    __half2 lo = __floats2half2_rn(v.x, v.y);
    __half2 hi = __floats2half2_rn(v.z, v.w);
    uint2 r;
    r.x = *(uint32_t*)&lo;
    r.y = *(uint32_t*)&hi;
    return r;
}
__device__ __forceinline__ uint32_t packh2(float x, float y) {
    __half2 h = __floats2half2_rn(x, y);
    return *(uint32_t*)&h;
}
__device__ __forceinline__ void cp16(uint32_t dst, const void* src) {
    asm volatile("cp.async.cg.shared.global [%0], [%1], 16;" :: "r"(dst), "l"(src));
}
__device__ __forceinline__ void cp_commit() {
    asm volatile("cp.async.commit_group;");
}

// ---------------------------------------------------------------------------
// Weight conversion / packing
// ---------------------------------------------------------------------------
__global__ void pack_qkv(const float* __restrict__ qw, const float* __restrict__ kw,
                         const float* __restrict__ vw, const float* __restrict__ qb,
                         const float* __restrict__ kb, const float* __restrict__ vb,
                         __half* __restrict__ w16, float* __restrict__ b) {
    int idx = blockIdx.x * blockDim.x + threadIdx.x;
    int e = idx * 4;
    if (e < D * D) {
        int k = e / D, n = e % D;
        size_t o = (size_t)k * QKVN + n;
        *(uint2*)&w16[o]        = f4_to_h4(*(const float4*)(qw + e));
        *(uint2*)&w16[o + 1152] = f4_to_h4(*(const float4*)(kw + e));
        *(uint2*)&w16[o + 2304] = f4_to_h4(*(const float4*)(vw + e));
    }
    if (idx < D) {
        b[idx]        = qb[idx];
        b[idx + 1152] = kb[idx];
        b[idx + 2304] = vb[idx];
    }
}
__global__ void conv_h(const float* __restrict__ src, __half* __restrict__ dst, int n4) {
    int i = blockIdx.x * blockDim.x + threadIdx.x;
    if (i < n4)
        *(uint2*)&dst[(size_t)i * 4] = f4_to_h4(*(const float4*)(src + (size_t)i * 4));
}

// ---------------------------------------------------------------------------
// LayerNorm: fp32 in, fp16 out
// ---------------------------------------------------------------------------
__global__ void ln_kernel(const float* __restrict__ X, const float* __restrict__ gamma,
                          const float* __restrict__ beta, __half* __restrict__ Y) {
    int row = blockIdx.x;
    int tid = threadIdx.x;
    float4 v = ((const float4*)(X + (size_t)row * D))[tid];
    float s  = v.x + v.y + v.z + v.w;
    float sq = v.x * v.x + v.y * v.y + v.z * v.z + v.w * v.w;
    #pragma unroll
    for (int o = 16; o > 0; o >>= 1) {
        s  += __shfl_down_sync(0xffffffffu, s,  o);
        sq += __shfl_down_sync(0xffffffffu, sq, o);
    }
    __shared__ float ss[9], ssq[9];
    int w = tid >> 5, l = tid & 31;
    if (l == 0) { ss[w] = s; ssq[w] = sq; }
    __syncthreads();
    float ts = 0.f, tsq = 0.f;
    #pragma unroll
    for (int i = 0; i < 9; i++) { ts += ss[i]; tsq += ssq[i]; }
    const float invD = 1.0f / (float)D;
    float mean = ts * invD;
    float var  = tsq * invD - mean * mean;
    float rinv = rsqrtf(var + 1e-5f);
    float4 g = ((const float4*)gamma)[tid];
    float4 b = ((const float4*)beta)[tid];
    float4 o;
    o.x = (v.x - mean) * rinv * g.x + b.x;
    o.y = (v.y - mean) * rinv * g.y + b.y;
    o.z = (v.z - mean) * rinv * g.z + b.z;
    o.w = (v.w - mean) * rinv * g.w + b.w;
    *(uint2*)(Y + (size_t)row * D + tid * 4) = f4_to_h4(o);
}

// ---------------------------------------------------------------------------
// fp16 GEMM, 4-stage cp.async pipeline (R8 known-good, unchanged)
// ---------------------------------------------------------------------------
#define GSTG 4
#define AP_  40
#define BP_  136
#define A_ST (128 * AP_)
#define B_ST (32 * BP_)
#define GEMM_SMEM ((GSTG * (A_ST + B_ST)) * 2)

__global__ __launch_bounds__(256, 2)
void gemm_h(const __half* __restrict__ A, const __half* __restrict__ W,
            const float* __restrict__ bias, const float* __restrict__ res,
            void* __restrict__ Cv, int M, int N, int K, int lda,
            int gelu_act, int out_half)
{
    extern __shared__ __half dsm[];
    __half* Asm = dsm;
    __half* Bsm = dsm + GSTG * A_ST;

    int tid  = threadIdx.x;
    int lane = tid & 31;
    int warp = tid >> 5;
    int mwbase = (warp & 1) * 64;
    int nwbase = (warp >> 1) * 32;
    int brow = blockIdx.y * 128;
    int bcol = blockIdx.x * 128;
    int g4 = lane >> 2;
    int t4 = lane & 3;

    int a_row = tid >> 1;
    int a_c   = (tid & 1) * 16;
    int b_row = tid >> 3;
    int b_c   = (tid & 7) * 16;

    const __half* Ap = A + (size_t)(brow + a_row) * lda + a_c;
    const __half* Wp = W + (size_t)b_row * N + bcol + b_c;

    uint32_t as_base = smem_u32(Asm) + (a_row * AP_ + a_c) * 2;
    uint32_t bs_base = smem_u32(Bsm) + (b_row * BP_ + b_c) * 2;

    float acc[4][4][4];
    #pragma unroll
    for (int mt = 0; mt < 4; mt++)
        #pragma unroll
        for (int nt = 0; nt < 4; nt++)
            #pragma unroll
            for (int r = 0; r < 4; r++) acc[mt][nt][r] = 0.f;

    int nk = K / 32;
    #pragma unroll
    for (int s = 0; s < GSTG - 1; s++) {
        const __half* ap = Ap + s * 32;
        const __half* wp = Wp + (size_t)s * 32 * N;
        uint32_t ad = as_base + s * A_ST * 2;
        uint32_t bd = bs_base + s * B_ST * 2;
        cp16(ad,      ap);
        cp16(ad + 16, ap + 8);
        cp16(bd,      wp);
        cp16(bd + 16, wp + 8);
        cp_commit();
    }

    for (int kt = 0; kt < nk; kt++) {
        int cur = kt & (GSTG - 1);
        asm volatile("cp.async.wait_group %0;" :: "n"(GSTG - 2));
        __syncthreads();
        if (kt + GSTG - 1 < nk) {
            int nst = (kt + GSTG - 1) & (GSTG - 1);
            const __half* ap = Ap + (kt + GSTG - 1) * 32;
            const __half* wp = Wp + (size_t)(kt + GSTG - 1) * 32 * N;
            uint32_t ad = as_base + nst * A_ST * 2;
            uint32_t bd = bs_base + nst * B_ST * 2;
            cp16(ad,      ap);
            cp16(ad + 16, ap + 8);
            cp16(bd,      wp);
            cp16(bd + 16, wp + 8);
        }
        cp_commit();
        const __half* Abuf = Asm + cur * A_ST;
        const __half* Bbuf = Bsm + cur * B_ST;
        #pragma unroll
        for (int kk = 0; kk < 32; kk += 16) {
            uint32_t bfr[4][2];
            #pragma unroll
            for (int np = 0; np < 2; np++) {
                int kr = kk + (lane & 7) + ((lane >> 3) & 1) * 8;
                int nc = nwbase + np * 16 + (lane >> 4) * 8;
                uint32_t r[4];
                ldsm_x4_t(r, smem_u32(Bbuf + kr * BP_ + nc));
                bfr[np * 2][0] = r[0]; bfr[np * 2][1] = r[1];
                bfr[np * 2 + 1][0] = r[2]; bfr[np * 2 + 1][1] = r[3];
            }
            #pragma unroll
            for (int mt = 0; mt < 4; mt++) {
                int ar = mwbase + mt * 16 + (lane & 15);
                int ac = kk + (lane >> 4) * 8;
                uint32_t a[4];
                ldsm_x4(a, smem_u32(Abuf + ar * AP_ + ac));
                #pragma unroll
                for (int nt = 0; nt < 4; nt++)
                    mma_f16(acc[mt][nt], a, bfr[nt][0], bfr[nt][1]);
            }
        }
    }

    __syncthreads();
    #pragma unroll
    for (int mt = 0; mt < 4; mt++) {
        #pragma unroll
        for (int nt = 0; nt < 4; nt++) {
            int col  = bcol + nwbase + nt * 8 + t4 * 2;
            float bx = bias[col], by = bias[col + 1];
            #pragma unroll
            for (int half = 0; half < 2; half++) {
                size_t row = (size_t)(brow + mwbase + mt * 16 + g4 + half * 8);
                float ox = acc[mt][nt][half * 2 + 0] + bx;
                float oy = acc[mt][nt][half * 2 + 1] + by;
                if (gelu_act) {
                    ox = 0.5f * ox * (1.0f + erff(ox * 0.70710678118f));
                    oy = 0.5f * oy * (1.0f + erff(oy * 0.70710678118f));
                }
                if (out_half) {
                    __half* Ch = (__half*)Cv;
                    *(__half2*)(Ch + row * N + col) = __floats2half2_rn(ox, oy);
                } else {
                    if (res) {
                        const float2 r = *(const float2*)(res + row * N + col);
                        ox += r.x; oy += r.y;
                    }
                    *(float2*)((float*)Cv + row * N + col) = make_float2(ox, oy);
                }
            }
        }
    }
}

// ---------------------------------------------------------------------------
// Flash attention with cp.async double-buffered K/V blocks.
// Grid: (SEQ/128, NB*NH). 256 threads (8 warps), warp owns 16 q-rows.
// Smem: Q[128][88] + K[2][128][88] + V[2][128][88] = 112,640 B.
// ---------------------------------------------------------------------------
#define FAP 88
#define FTS (128 * FAP)    // halves per tile slot

__global__ __launch_bounds__(256, 1)
void flash_attn(const __half* __restrict__ QKV, __half* __restrict__ O) {
    extern __shared__ __half fsm[];
    __half (*Qs)[FAP] = (__half (*)[FAP])fsm;
    __half* Kbuf[2] = { fsm + FTS,     fsm + 2 * FTS };
    __half* Vbuf[2] = { fsm + 3 * FTS, fsm + 4 * FTS };

    int bh = blockIdx.y;
    int b = bh >> 4, h = bh & 15;
    int row0 = blockIdx.x * 128;
    const __half* qbase = QKV + (size_t)b * SEQ * QKVN + h * HD;
    const __half* kbase = qbase + 1152;
    const __half* vbase = qbase + 2304;
    int tid = threadIdx.x;
    int lane = tid & 31;
    int warp = tid >> 5;
    int g4 = lane >> 2;
    int t4 = lane & 3;

    // stage Q (scale folded), zero-pad d-cols 72..79 of Q and both K buffers
    {
        const __half2 sc2 = __float2half2_rn(0.117851130198f);
        for (int i = tid; i < 128 * 18; i += 256) {
            int r = i / 18, c = (i % 18) * 4;
            uint2 u = *(const uint2*)(qbase + (size_t)(row0 + r) * QKVN + c);
            __half2 lo = __hmul2(*(__half2*)&u.x, sc2);
            __half2 hi = __hmul2(*(__half2*)&u.y, sc2);
            uint2 o;
            o.x = *(uint32_t*)&lo;
            o.y = *(uint32_t*)&hi;
            *(uint2*)&Qs[r][c] = o;
        }
        for (int i = tid; i < 128 * 2; i += 256) {
            int r = i >> 1, c = 72 + (i & 1) * 4;
            uint2 z = make_uint2(0u, 0u);
            *(uint2*)&Qs[r][c] = z;
            *(uint2*)&Kbuf[0][r * FAP + c] = z;
            *(uint2*)&Kbuf[1][r * FAP + c] = z;
        }
    }

    // prefetch K/V block 0 into buffer 0 (9 x 16B per 72-half row)
    for (int i = tid; i < 128 * 9; i += 256) {
        int r = i / 9, c16 = i % 9;
        uint32_t doff = (r * FAP + c16 * 8) * 2;
        cp16(smem_u32(Kbuf[0]) + doff, kbase + (size_t)r * QKVN + c16 * 8);
        cp16(smem_u32(Vbuf[0]) + doff, vbase + (size_t)r * QKVN + c16 * 8);
    }
    cp_commit();
    asm volatile("cp.async.wait_group 0;");
    __syncthreads();

    // preload Q fragments
    uint32_t qf[5][4];
    #pragma unroll
    for (int kc = 0; kc < 5; kc++) {
        int ar = warp * 16 + (lane & 15);
        int ac = kc * 16 + (lane >> 4) * 8;
        ldsm_x4(qf[kc], smem_u32(&Qs[ar][ac]));
    }

    float m0 = -1e30f, m1 = -1e30f, l0 = 0.f, l1 = 0.f;
    float o[10][4];
    #pragma unroll
    for (int nt = 0; nt < 10; nt++)
        #pragma unroll
        for (int r = 0; r < 4; r++) o[nt][r] = 0.f;

    for (int jb = 0; jb < 8; jb++) {
        int buf = jb & 1;
        const __half* Ks = Kbuf[buf];
        const __half* Vs = Vbuf[buf];
        // prefetch next block into alternate buffer (overlaps with compute)
        if (jb + 1 < 8) {
            int nb = buf ^ 1;
            int j0 = (jb + 1) * 128;
            for (int i = tid; i < 128 * 9; i += 256) {
                int r = i / 9, c16 = i % 9;
                uint32_t doff = (r * FAP + c16 * 8) * 2;
                cp16(smem_u32(Kbuf[nb]) + doff, kbase + (size_t)(j0 + r) * QKVN + c16 * 8);
                cp16(smem_u32(Vbuf[nb]) + doff, vbase + (size_t)(j0 + r) * QKVN + c16 * 8);
            }
            cp_commit();
        }

        // S = Q K^T  (warp computes 16x128)
        float s[16][4];
        #pragma unroll
        for (int nt = 0; nt < 16; nt++)
            #pragma unroll
            for (int r = 0; r < 4; r++) s[nt][r] = 0.f;
        #pragma unroll
        for (int np = 0; np < 8; np++) {
            int nr = np * 16 + (lane & 7) + (lane >> 4) * 8;
            #pragma unroll
            for (int kc = 0; kc < 5; kc++) {
                int nc = kc * 16 + ((lane >> 3) & 1) * 8;
                uint32_t r[4];
                ldsm_x4(r, smem_u32(Ks + nr * FAP + nc));
                mma_f16(s[np * 2],     qf[kc], r[0], r[1]);
                mma_f16(s[np * 2 + 1], qf[kc], r[2], r[3]);
            }
        }

        // online softmax (rows g4 and g4+8)
        float cm0 = -1e30f, cm1 = -1e30f;
        #pragma unroll
        for (int nt = 0; nt < 16; nt++) {
            cm0 = fmaxf(cm0, fmaxf(s[nt][0], s[nt][1]));
            cm1 = fmaxf(cm1, fmaxf(s[nt][2], s[nt][3]));
        }
        cm0 = fmaxf(cm0, __shfl_xor_sync(0xffffffffu, cm0, 1));
        cm0 = fmaxf(cm0, __shfl_xor_sync(0xffffffffu, cm0, 2));
        cm1 = fmaxf(cm1, __shfl_xor_sync(0xffffffffu, cm1, 1));
        cm1 = fmaxf(cm1, __shfl_xor_sync(0xffffffffu, cm1, 2));
        float nm0 = fmaxf(m0, cm0);
        float nm1 = fmaxf(m1, cm1);
        float f0 = __expf(m0 - nm0);
        float f1 = __expf(m1 - nm1);
        m0 = nm0; m1 = nm1;
        float sum0 = 0.f, sum1 = 0.f;
        #pragma unroll
        for (int nt = 0; nt < 16; nt++) {
            s[nt][0] = __expf(s[nt][0] - nm0);
            s[nt][1] = __expf(s[nt][1] - nm0);
            s[nt][2] = __expf(s[nt][2] - nm1);
            s[nt][3] = __expf(s[nt][3] - nm1);
            sum0 += s[nt][0] + s[nt][1];
            sum1 += s[nt][2] + s[nt][3];
        }
        l0 = l0 * f0 + sum0;
        l1 = l1 * f1 + sum1;
        #pragma unroll
        for (int nt = 0; nt < 10; nt++) {
            o[nt][0] *= f0; o[nt][1] *= f0;
            o[nt][2] *= f1; o[nt][3] *= f1;
        }

        // O += P V  (P from registers)
        #pragma unroll
        for (int kc2 = 0; kc2 < 8; kc2++) {
            uint32_t a[4];
            a[0] = packh2(s[kc2 * 2][0],     s[kc2 * 2][1]);
            a[1] = packh2(s[kc2 * 2][2],     s[kc2 * 2][3]);
            a[2] = packh2(s[kc2 * 2 + 1][0], s[kc2 * 2 + 1][1]);
            a[3] = packh2(s[kc2 * 2 + 1][2], s[kc2 * 2 + 1][3]);
            int kr = kc2 * 16 + (lane & 7) + ((lane >> 3) & 1) * 8;
            #pragma unroll
            for (int np = 0; np < 5; np++) {
                int nc = np * 16 + (lane >> 4) * 8;
                uint32_t r[4];
                ldsm_x4_t(r, smem_u32(Vs + kr * FAP + nc));
                mma_f16(o[np * 2],     a, r[0], r[1]);
                mma_f16(o[np * 2 + 1], a, r[2], r[3]);
            }
        }
        if (jb + 1 < 8) {
            asm volatile("cp.async.wait_group 0;");
            __syncthreads();
        }
    }

    // finalize
    l0 += __shfl_xor_sync(0xffffffffu, l0, 1);
    l0 += __shfl_xor_sync(0xffffffffu, l0, 2);
    l1 += __shfl_xor_sync(0xffffffffu, l1, 1);
    l1 += __shfl_xor_sync(0xffffffffu, l1, 2);
    float inv0 = 1.0f / l0;
    float inv1 = 1.0f / l1;
    #pragma unroll
    for (int nt = 0; nt < 9; nt++) {
        int col = h * HD + nt * 8 + t4 * 2;
        size_t r = (size_t)b * SEQ + row0 + warp * 16 + g4;
        *(__half2*)(O + r * D + col)       = __floats2half2_rn(o[nt][0] * inv0, o[nt][1] * inv0);
        *(__half2*)(O + (r + 8) * D + col) = __floats2half2_rn(o[nt][2] * inv1, o[nt][3] * inv1);
    }
}

// ---------------------------------------------------------------------------
// Launch
// ---------------------------------------------------------------------------
extern "C" void kernel_launch(void* const* d_in, const int* in_sizes, int n_in,
                              void* d_out, int out_size) {
    const float* hs    = (const float*)d_in[0];
    const float* ln1_w = (const float*)d_in[1];
    const float* ln1_b = (const float*)d_in[2];
    const float* q_w   = (const float*)d_in[3];
    const float* q_b   = (const float*)d_in[4];
    const float* k_w   = (const float*)d_in[5];
    const float* k_b   = (const float*)d_in[6];
    const float* v_w   = (const float*)d_in[7];
    const float* v_b   = (const float*)d_in[8];
    const float* o_w   = (const float*)d_in[9];
    const float* o_b   = (const float*)d_in[10];
    const float* ln2_w = (const float*)d_in[11];
    const float* ln2_b = (const float*)d_in[12];
    const float* fc1_w = (const float*)d_in[13];
    const float* fc1_b = (const float*)d_in[14];
    const float* fc2_w = (const float*)d_in[15];
    const float* fc2_b = (const float*)d_in[16];
    float* out = (float*)d_out;

    __half *xln, *qkv, *ao, *ff, *wqkv, *wo, *wfc1, *wfc2;
    float *h2, *bqkv;
    cudaGetSymbolAddress((void**)&xln,  g_xln);
    cudaGetSymbolAddress((void**)&qkv,  g_qkv);
    cudaGetSymbolAddress((void**)&ao,   g_ao);
    cudaGetSymbolAddress((void**)&h2,   g_h2);
    cudaGetSymbolAddress((void**)&ff,   g_ff);
    cudaGetSymbolAddress((void**)&wqkv, g_wqkv);
    cudaGetSymbolAddress((void**)&bqkv, g_bqkv);
    cudaGetSymbolAddress((void**)&wo,   g_wo);
    cudaGetSymbolAddress((void**)&wfc1, g_wfc1);
    cudaGetSymbolAddress((void**)&wfc2, g_wfc2);

    const int FA_SMEM = 5 * FTS * (int)sizeof(__half);          // 112,640 B
    cudaFuncSetAttribute(flash_attn, cudaFuncAttributeMaxDynamicSharedMemorySize,
                         FA_SMEM);
    cudaFuncSetAttribute(gemm_h, cudaFuncAttributeMaxDynamicSharedMemorySize,
                         GEMM_SMEM);                            // 75,776 B

    // 0. weight conversion / packing
    pack_qkv<<<(D * D / 4 + 255) / 256, 256>>>(q_w, k_w, v_w, q_b, k_b, v_b, wqkv, bqkv);
    conv_h<<<(D * D / 4 + 255) / 256, 256>>>(o_w, wo, D * D / 4);
    conv_h<<<(D * FFD / 4 + 255) / 256, 256>>>(fc1_w, wfc1, D * FFD / 4);
    conv_h<<<(FFD * D / 4 + 255) / 256, 256>>>(fc2_w, wfc2, FFD * D / 4);

    // 1. LN1 -> fp16
    ln_kernel<<<TOK, 288>>>(hs, ln1_w, ln1_b, xln);
    // 2. fused QKV projection
    gemm_h<<<dim3(QKVN / 128, TOK / 128), 256, GEMM_SMEM>>>(xln, wqkv, bqkv, nullptr, qkv,
                                                            TOK, QKVN, D, D, 0, 1);
    // 3-5. fused attention (cp.async double-buffered K/V)
    flash_attn<<<dim3(SEQ / 128, NB * NH), 256, FA_SMEM>>>(qkv, ao);
    // 6. O projection + residual1 (fp32 out)
    gemm_h<<<dim3(D / 128, TOK / 128), 256, GEMM_SMEM>>>(ao, wo, o_b, hs, h2,
                                                         TOK, D, D, D, 0, 0);
    // 7. LN2 -> fp16
    ln_kernel<<<TOK, 288>>>(h2, ln2_w, ln2_b, xln);
    // 8. FC1 + GELU (fp16 out)
    gemm_h<<<dim3(FFD / 128, TOK / 128), 256, GEMM_SMEM>>>(xln, wfc1, fc1_b, nullptr, ff,
                                                           TOK, FFD, D, D, 1, 1);
    // 9. FC2 + residual2 (fp32 out)
    gemm_h<<<dim3(D / 128, TOK / 128), 256, GEMM_SMEM>>>(ff, wfc2, fc2_b, h2, out,
                                                         TOK, D, FFD, FFD, 0, 0);
}